// round 2
// baseline (speedup 1.0000x reference)
#include <cuda_runtime.h>
#include <cuda_pipeline.h>
#include <cstdint>

#define N_VEH    40000
#define N_PATHS  400000
#define TILE_M   128
#define XS       164          // xbuf/tbuf row stride in floats (conflict-free: 164 % 32 == 4)
#define WS       20           // weight chunk row stride in floats (20 % 32 -> conflict-free B loads)
#define NTHREADS 512

// Scratch: precomputed per-vehicle partials [N_VEH][320]:
//   cols 0..159  = w1[:,160:320] @ [actors[v] || Z_act[v]]
//   cols 160..319= wt[:,160:320] @ [actors[v] || Z_act[v]]
__device__ float g_PV[(size_t)N_VEH * 320];

__device__ __forceinline__ unsigned tf32u(float x) {
    unsigned y;
    asm("cvt.rna.tf32.f32 %0, %1;" : "=r"(y) : "f"(x));
    return y;
}

__device__ __forceinline__ void mma8(float* d, const unsigned* a, const unsigned* b) {
    asm volatile(
        "mma.sync.aligned.m16n8k8.row.col.f32.tf32.tf32.f32 "
        "{%0,%1,%2,%3}, {%4,%5,%6,%7}, {%8,%9}, {%0,%1,%2,%3};\n"
        : "+f"(d[0]), "+f"(d[1]), "+f"(d[2]), "+f"(d[3])
        : "r"(a[0]), "r"(a[1]), "r"(a[2]), "r"(a[3]), "r"(b[0]), "r"(b[1]));
}

// One GEMM pass: acc[2][5][4] += X(128x160, smem, tf32-rounded) @ W(160x160 slice)^T
// Warp layout: 16 warps as 4(m) x 4(n); warp tile 32 rows x 40 cols.
// W streamed from global in K-chunks of 16 via cp.async double buffer.
__device__ __forceinline__ void gemm_pass(
    float acc[2][5][4],
    const float* __restrict__ Wg, int gstride, int koff,
    const float* __restrict__ xs, float* ws, int tid)
{
    const int lane = tid & 31;
    const int warp = tid >> 5;
    const int wm = warp & 3;
    const int wn = warp >> 2;
    const int qr = lane >> 2, qc = lane & 3;
    const int rbase = wm * 32 + qr;
    const int nbase = wn * 40 + qr;

    // stage chunk 0
    {
        const float* src0 = Wg + koff;
        for (int c = tid; c < 640; c += NTHREADS) {
            int n = c >> 2, p = c & 3;
            __pipeline_memcpy_async(ws + n * WS + p * 4, src0 + n * gstride + p * 4, 16);
        }
        __pipeline_commit();
    }

    #pragma unroll 1
    for (int i = 0; i < 10; i++) {
        if (i + 1 < 10) {
            const float* src = Wg + koff + (i + 1) * 16;
            float* dst = ws + ((i + 1) & 1) * 3200;
            for (int c = tid; c < 640; c += NTHREADS) {
                int n = c >> 2, p = c & 3;
                __pipeline_memcpy_async(dst + n * WS + p * 4, src + n * gstride + p * 4, 16);
            }
            __pipeline_commit();
            __pipeline_wait_prior(1);
        } else {
            __pipeline_wait_prior(0);
        }
        __syncthreads();

        const float* wb = ws + (i & 1) * 3200;
        #pragma unroll
        for (int half = 0; half < 2; half++) {
            const int kk = i * 16 + half * 8 + qc;   // absolute K index into xs
            const int kl = half * 8 + qc;            // local K index into chunk
            unsigned a[2][4];
            #pragma unroll
            for (int mf = 0; mf < 2; mf++) {
                int r = rbase + mf * 16;
                a[mf][0] = __float_as_uint(xs[r * XS + kk]);
                a[mf][1] = __float_as_uint(xs[(r + 8) * XS + kk]);
                a[mf][2] = __float_as_uint(xs[r * XS + kk + 4]);
                a[mf][3] = __float_as_uint(xs[(r + 8) * XS + kk + 4]);
            }
            unsigned b[5][2];
            #pragma unroll
            for (int nf = 0; nf < 5; nf++) {
                int n = nbase + nf * 8;
                b[nf][0] = tf32u(wb[n * WS + kl]);
                b[nf][1] = tf32u(wb[n * WS + kl + 4]);
            }
            #pragma unroll
            for (int mf = 0; mf < 2; mf++)
                #pragma unroll
                for (int nf = 0; nf < 5; nf++)
                    mma8(acc[mf][nf], a[mf], b[nf]);
        }
        __syncthreads();
    }
}

// Kernel 1: per-vehicle partial sums into g_PV
__global__ void __launch_bounds__(NTHREADS, 1)
veh_pre_kernel(const float* __restrict__ actors, const float* __restrict__ Z_act,
               const float* __restrict__ w1, const float* __restrict__ wt)
{
    extern __shared__ float sm[];
    float* xbuf = sm;                       // 128 * 164 floats
    float* wbuf = xbuf + TILE_M * XS;       // 2 * 3200 floats
    const int tid = threadIdx.x;
    const int v0 = blockIdx.x * TILE_M;

    for (int idx = tid; idx < TILE_M * 160; idx += NTHREADS) {
        int r = idx / 160, c = idx - r * 160;
        int v = v0 + r;
        float val = 0.0f;
        if (v < N_VEH)
            val = (c < 128) ? actors[(size_t)v * 128 + c]
                            : Z_act[(size_t)v * 32 + (c - 128)];
        xbuf[r * XS + c] = __uint_as_float(tf32u(val));
    }
    __syncthreads();

    const int lane = tid & 31, warp = tid >> 5;
    const int wm = warp & 3, wn = warp >> 2;
    const int qr = lane >> 2, qc = lane & 3;
    const int rb = wm * 32 + qr;
    const int cb = wn * 40 + 2 * qc;

    #pragma unroll 1
    for (int pass = 0; pass < 2; pass++) {
        const float* Wg = pass ? wt : w1;
        const int coloff = pass ? 160 : 0;
        float acc[2][5][4] = {};
        gemm_pass(acc, Wg, 320, 160, xbuf, wbuf, tid);
        #pragma unroll
        for (int mf = 0; mf < 2; mf++) {
            int r = rb + mf * 16;
            int vA = v0 + r, vB = v0 + r + 8;
            #pragma unroll
            for (int nf = 0; nf < 5; nf++) {
                int c = cb + nf * 8;
                if (vA < N_VEH)
                    *(float2*)(g_PV + (size_t)vA * 320 + coloff + c) =
                        make_float2(acc[mf][nf][0], acc[mf][nf][1]);
                if (vB < N_VEH)
                    *(float2*)(g_PV + (size_t)vB * 320 + coloff + c) =
                        make_float2(acc[mf][nf][2], acc[mf][nf][3]);
            }
        }
        __syncthreads();
    }
}

// Kernel 2: fused per-path pipeline
__global__ void __launch_bounds__(NTHREADS, 1)
path_main_kernel(
    const float* __restrict__ paths, const float* __restrict__ Z_pat,
    const int* __restrict__ u,
    const float* __restrict__ w1, const float* __restrict__ w2,
    const float* __restrict__ wt,
    const float* __restrict__ g1w, const float* __restrict__ g1b,
    const float* __restrict__ g2w, const float* __restrict__ g2b,
    const float* __restrict__ wh, const float* __restrict__ bh,
    float* __restrict__ out)
{
    extern __shared__ float sm[];
    float* xbuf = sm;                         // 128*164  (xp, later h1r)
    float* tbuf = xbuf + TILE_M * XS;         // 128*164  (skip branch t)
    float* wbuf = tbuf + TILE_M * XS;         // 6400
    int*   u_s  = (int*)(wbuf + 6400);        // 128
    float* rsum = (float*)(u_s + 128);        // 128
    float* rssq = rsum + 128;                 // 128
    float* oacc = rssq + 128;                 // 128
    float* p1w = oacc + 128;                  // 5 x 160 params
    float* p1b = p1w + 160;
    float* p2w = p1b + 160;
    float* p2b = p2w + 160;
    float* pwh = p2b + 160;

    const int tid = threadIdx.x;
    const int row0 = blockIdx.x * TILE_M;

    for (int i = tid; i < 160; i += NTHREADS) {
        p1w[i] = g1w[i]; p1b[i] = g1b[i];
        p2w[i] = g2w[i]; p2b[i] = g2b[i];
        pwh[i] = wh[i];
    }
    if (tid < 128) {
        u_s[tid] = u[row0 + tid];
        rsum[tid] = 0.0f; rssq[tid] = 0.0f; oacc[tid] = 0.0f;
    }
    for (int idx = tid; idx < TILE_M * 160; idx += NTHREADS) {
        int r = idx / 160, c = idx - r * 160;
        float v = (c < 128) ? paths[(size_t)(row0 + r) * 128 + c]
                            : Z_pat[(size_t)(row0 + r) * 32 + (c - 128)];
        xbuf[r * XS + c] = __uint_as_float(tf32u(v));
    }
    __syncthreads();

    const int lane = tid & 31, warp = tid >> 5;
    const int wm = warp & 3, wn = warp >> 2;
    const int qr = lane >> 2, qc = lane & 3;
    const int rb = wm * 32 + qr;
    const int cb = wn * 40 + 2 * qc;

    // ---- pass T: t = xp @ wt_p^T + PV[u][160:320] -> tbuf ----
    {
        float acc[2][5][4] = {};
        gemm_pass(acc, wt, 320, 0, xbuf, wbuf, tid);
        #pragma unroll
        for (int mf = 0; mf < 2; mf++) {
            int r = rb + mf * 16;
            const float* pv0 = g_PV + (size_t)u_s[r] * 320 + 160 + cb;
            const float* pv1 = g_PV + (size_t)u_s[r + 8] * 320 + 160 + cb;
            #pragma unroll
            for (int nf = 0; nf < 5; nf++) {
                float2 v0 = *(const float2*)(pv0 + nf * 8);
                float2 v1 = *(const float2*)(pv1 + nf * 8);
                *(float2*)(tbuf + r * XS + cb + nf * 8) =
                    make_float2(acc[mf][nf][0] + v0.x, acc[mf][nf][1] + v0.y);
                *(float2*)(tbuf + (r + 8) * XS + cb + nf * 8) =
                    make_float2(acc[mf][nf][2] + v1.x, acc[mf][nf][3] + v1.y);
            }
        }
    }

    // ---- pass 1: h1 = xp @ w1_p^T + PV[u][0:160], GN1, ReLU -> xbuf ----
    {
        float acc[2][5][4] = {};
        gemm_pass(acc, w1, 320, 0, xbuf, wbuf, tid);
        #pragma unroll
        for (int mf = 0; mf < 2; mf++) {
            int r = rb + mf * 16;
            const float* pv0 = g_PV + (size_t)u_s[r] * 320 + cb;
            const float* pv1 = g_PV + (size_t)u_s[r + 8] * 320 + cb;
            #pragma unroll
            for (int nf = 0; nf < 5; nf++) {
                float2 v0 = *(const float2*)(pv0 + nf * 8);
                float2 v1 = *(const float2*)(pv1 + nf * 8);
                acc[mf][nf][0] += v0.x; acc[mf][nf][1] += v0.y;
                acc[mf][nf][2] += v1.x; acc[mf][nf][3] += v1.y;
            }
        }
        // GN1 stats
        #pragma unroll
        for (int mf = 0; mf < 2; mf++)
            #pragma unroll
            for (int h = 0; h < 2; h++) {
                float s = 0.0f, ss = 0.0f;
                #pragma unroll
                for (int nf = 0; nf < 5; nf++) {
                    float a0 = acc[mf][nf][2 * h], a1 = acc[mf][nf][2 * h + 1];
                    s += a0 + a1; ss += a0 * a0 + a1 * a1;
                }
                s  += __shfl_xor_sync(0xffffffffu, s, 1);
                ss += __shfl_xor_sync(0xffffffffu, ss, 1);
                s  += __shfl_xor_sync(0xffffffffu, s, 2);
                ss += __shfl_xor_sync(0xffffffffu, ss, 2);
                if (qc == 0) {
                    int r = rb + mf * 16 + 8 * h;
                    atomicAdd(&rsum[r], s);
                    atomicAdd(&rssq[r], ss);
                }
            }
        __syncthreads();
        // normalize + relu, overwrite xbuf with h1r (tf32-rounded)
        #pragma unroll
        for (int mf = 0; mf < 2; mf++)
            #pragma unroll
            for (int h = 0; h < 2; h++) {
                int r = rb + mf * 16 + 8 * h;
                float mean = rsum[r] * (1.0f / 160.0f);
                float var  = rssq[r] * (1.0f / 160.0f) - mean * mean;
                float rstd = rsqrtf(var + 1e-5f);
                #pragma unroll
                for (int nf = 0; nf < 5; nf++)
                    #pragma unroll
                    for (int e = 0; e < 2; e++) {
                        int col = cb + nf * 8 + e;
                        float v = (acc[mf][nf][2 * h + e] - mean) * rstd * p1w[col] + p1b[col];
                        v = fmaxf(v, 0.0f);
                        xbuf[r * XS + col] = __uint_as_float(tf32u(v));
                    }
            }
    }
    __syncthreads();
    if (tid < 128) { rsum[tid] = 0.0f; rssq[tid] = 0.0f; }

    // ---- pass 2: h2 = h1r @ w2^T, GN2, +t, ReLU, head ----
    {
        float acc[2][5][4] = {};
        gemm_pass(acc, w2, 160, 0, xbuf, wbuf, tid);
        #pragma unroll
        for (int mf = 0; mf < 2; mf++)
            #pragma unroll
            for (int h = 0; h < 2; h++) {
                float s = 0.0f, ss = 0.0f;
                #pragma unroll
                for (int nf = 0; nf < 5; nf++) {
                    float a0 = acc[mf][nf][2 * h], a1 = acc[mf][nf][2 * h + 1];
                    s += a0 + a1; ss += a0 * a0 + a1 * a1;
                }
                s  += __shfl_xor_sync(0xffffffffu, s, 1);
                ss += __shfl_xor_sync(0xffffffffu, ss, 1);
                s  += __shfl_xor_sync(0xffffffffu, s, 2);
                ss += __shfl_xor_sync(0xffffffffu, ss, 2);
                if (qc == 0) {
                    int r = rb + mf * 16 + 8 * h;
                    atomicAdd(&rsum[r], s);
                    atomicAdd(&rssq[r], ss);
                }
            }
        __syncthreads();
        #pragma unroll
        for (int mf = 0; mf < 2; mf++)
            #pragma unroll
            for (int h = 0; h < 2; h++) {
                int r = rb + mf * 16 + 8 * h;
                float mean = rsum[r] * (1.0f / 160.0f);
                float var  = rssq[r] * (1.0f / 160.0f) - mean * mean;
                float rstd = rsqrtf(var + 1e-5f);
                float part = 0.0f;
                #pragma unroll
                for (int nf = 0; nf < 5; nf++) {
                    float2 tv = *(const float2*)(tbuf + r * XS + cb + nf * 8);
                    int col = cb + nf * 8;
                    float v0 = (acc[mf][nf][2 * h]     - mean) * rstd * p2w[col]     + p2b[col]     + tv.x;
                    float v1 = (acc[mf][nf][2 * h + 1] - mean) * rstd * p2w[col + 1] + p2b[col + 1] + tv.y;
                    v0 = fmaxf(v0, 0.0f);
                    v1 = fmaxf(v1, 0.0f);
                    part += v0 * pwh[col] + v1 * pwh[col + 1];
                }
                part += __shfl_xor_sync(0xffffffffu, part, 1);
                part += __shfl_xor_sync(0xffffffffu, part, 2);
                if (qc == 0) atomicAdd(&oacc[r], part);
            }
    }
    __syncthreads();
    if (tid < 128) out[row0 + tid] = oacc[tid] + bh[0];
}

extern "C" void kernel_launch(void* const* d_in, const int* in_sizes, int n_in,
                              void* d_out, int out_size)
{
    const float* actors = (const float*)d_in[0];
    const float* paths  = (const float*)d_in[1];
    const float* Z_act  = (const float*)d_in[2];
    const float* Z_pat  = (const float*)d_in[3];
    const int*   u      = (const int*)  d_in[4];
    const float* w1     = (const float*)d_in[5];
    const float* w2     = (const float*)d_in[6];
    const float* wt     = (const float*)d_in[7];
    const float* g1w    = (const float*)d_in[8];
    const float* g1b    = (const float*)d_in[9];
    const float* g2w    = (const float*)d_in[10];
    const float* g2b    = (const float*)d_in[11];
    const float* wh     = (const float*)d_in[12];
    const float* bh     = (const float*)d_in[13];
    float* out = (float*)d_out;

    const int smem1 = (TILE_M * XS + 2 * 3200) * 4;
    const int smem2 = (2 * TILE_M * XS + 2 * 3200) * 4 + 128 * 4 + 3 * 128 * 4 + 5 * 160 * 4;

    cudaFuncSetAttribute(veh_pre_kernel,  cudaFuncAttributeMaxDynamicSharedMemorySize, smem1);
    cudaFuncSetAttribute(path_main_kernel, cudaFuncAttributeMaxDynamicSharedMemorySize, smem2);

    veh_pre_kernel<<<(N_VEH + TILE_M - 1) / TILE_M, NTHREADS, smem1>>>(actors, Z_act, w1, wt);
    path_main_kernel<<<N_PATHS / TILE_M, NTHREADS, smem2>>>(
        paths, Z_pat, u, w1, w2, wt, g1w, g1b, g2w, g2b, wh, bh, out);
}

// round 3
// speedup vs baseline: 1.3466x; 1.3466x over previous
#include <cuda_runtime.h>
#include <cstdint>

#define N_VEH    40000
#define N_PATHS  400000
#define TILE_M   128
#define XS       164          // xbuf/tbuf row stride in floats (164 % 32 == 4 -> conflict-free)
#define NTHREADS 512

// Scratch: precomputed per-vehicle partials [N_VEH][320]:
//   cols 0..159  = w1[:,160:320] @ [actors[v] || Z_act[v]]
//   cols 160..319= wt[:,160:320] @ [actors[v] || Z_act[v]]
__device__ float g_PV[(size_t)N_VEH * 320];

// Packed tf32 weights, fragment-ordered + lane-interleaved:
// 5 slices x [wn:4][chunk:10][j:5][lane:32][4 floats] = 5 * 25600 floats.
// slice 0: w1[:,0:160], 1: wt[:,0:160], 2: w2, 3: w1[:,160:320], 4: wt[:,160:320]
__device__ __align__(16) float g_WPK[5 * 25600];

__device__ __forceinline__ unsigned tf32u(float x) {
    unsigned y;
    asm("cvt.rna.tf32.f32 %0, %1;" : "=r"(y) : "f"(x));
    return y;
}

__device__ __forceinline__ void mma8(float* d, const unsigned* a, const unsigned* b) {
    asm volatile(
        "mma.sync.aligned.m16n8k8.row.col.f32.tf32.tf32.f32 "
        "{%0,%1,%2,%3}, {%4,%5,%6,%7}, {%8,%9}, {%0,%1,%2,%3};\n"
        : "+f"(d[0]), "+f"(d[1]), "+f"(d[2]), "+f"(d[3])
        : "r"(a[0]), "r"(a[1]), "r"(a[2]), "r"(a[3]), "r"(b[0]), "r"(b[1]));
}

__device__ __forceinline__ void ldsm4(unsigned a[4], uint32_t addr) {
    asm volatile("ldmatrix.sync.aligned.m8n8.x4.shared.b16 {%0,%1,%2,%3}, [%4];"
                 : "=r"(a[0]), "=r"(a[1]), "=r"(a[2]), "=r"(a[3]) : "r"(addr));
}

// Pack kernel: convert weight slices to tf32 bits in fragment order.
// Linear index = (((slice*4+wn)*10 + chunk)*5 + j)*128 + lane*4 + e4
// t = j*4+e4 -> half = t/10, nf = (t%10)/2, e = t%2
// n = wn*40 + (lane>>2) + nf*8 ; k = chunk*16 + half*8 + (lane&3) + e*4
__global__ void pack_kernel(const float* __restrict__ w1,
                            const float* __restrict__ w2,
                            const float* __restrict__ wt)
{
    int idx = blockIdx.x * blockDim.x + threadIdx.x;
    if (idx >= 5 * 25600) return;
    int e4   = idx & 3;
    int lane = (idx >> 2) & 31;
    int rest = idx >> 7;
    int j    = rest % 5;  rest /= 5;
    int chunk= rest % 10; rest /= 10;
    int wn   = rest & 3;
    int slice= rest >> 2;

    int t    = j * 4 + e4;
    int half = t / 10;
    int rem  = t - half * 10;
    int nf   = rem >> 1;
    int e    = rem & 1;
    int n = wn * 40 + (lane >> 2) + nf * 8;
    int k = chunk * 16 + half * 8 + (lane & 3) + e * 4;

    const float* src; int gstride, koff;
    switch (slice) {
        case 0: src = w1; gstride = 320; koff = 0;   break;
        case 1: src = wt; gstride = 320; koff = 0;   break;
        case 2: src = w2; gstride = 160; koff = 0;   break;
        case 3: src = w1; gstride = 320; koff = 160; break;
        default:src = wt; gstride = 320; koff = 160; break;
    }
    g_WPK[idx] = __uint_as_float(tf32u(src[(size_t)n * gstride + koff + k]));
}

// GEMM pass: acc[2][5][4] += X(128x160 tf32 in smem) @ Wslice^T
// 16 warps = 4(m) x 4(n); warp tile 32 rows x 40 cols.
// A via ldmatrix.x4, B via coalesced LDG.128 from packed weights (reg double-buffered).
// No barriers, no smem for weights.
__device__ __forceinline__ void gemm_pass2(
    float acc[2][5][4],
    const float* __restrict__ pkbase,   // g_WPK + (slice*4+wn)*6400
    uint32_t xaddr0,                    // this lane's ldmatrix base addr (mf=0, k=0)
    int lane)
{
    const float4* bp = (const float4*)pkbase + lane;
    float4 b4[2][5];
    #pragma unroll
    for (int j = 0; j < 5; j++) b4[0][j] = __ldg(bp + j * 32);

    #pragma unroll
    for (int chunk = 0; chunk < 10; chunk++) {
        const int cur = chunk & 1;
        if (chunk < 9) {
            #pragma unroll
            for (int j = 0; j < 5; j++)
                b4[cur ^ 1][j] = __ldg(bp + ((chunk + 1) * 5 + j) * 32);
        }
        const unsigned* bu = (const unsigned*)b4[cur];
        #pragma unroll
        for (int half = 0; half < 2; half++) {
            unsigned a[2][4];
            uint32_t ad = xaddr0 + (uint32_t)((chunk * 16 + half * 8) * 4);
            ldsm4(a[0], ad);
            ldsm4(a[1], ad + 16 * XS * 4);
            #pragma unroll
            for (int mf = 0; mf < 2; mf++)
                #pragma unroll
                for (int nf = 0; nf < 5; nf++)
                    mma8(acc[mf][nf], a[mf], bu + half * 10 + nf * 2);
        }
    }
}

// Kernel 1: per-vehicle partial sums into g_PV (uses slices 3,4)
__global__ void __launch_bounds__(NTHREADS, 1)
veh_pre_kernel(const float* __restrict__ actors, const float* __restrict__ Z_act)
{
    extern __shared__ float sm[];
    float* xbuf = sm;                       // 128 * 164 floats
    const int tid = threadIdx.x;
    const int v0 = blockIdx.x * TILE_M;

    for (int idx = tid; idx < TILE_M * 160; idx += NTHREADS) {
        int r = idx / 160, c = idx - r * 160;
        int v = v0 + r;
        float val = 0.0f;
        if (v < N_VEH)
            val = (c < 128) ? actors[(size_t)v * 128 + c]
                            : Z_act[(size_t)v * 32 + (c - 128)];
        xbuf[r * XS + c] = __uint_as_float(tf32u(val));
    }
    __syncthreads();

    const int lane = tid & 31, warp = tid >> 5;
    const int wm = warp & 3, wn = warp >> 2;
    const int qr = lane >> 2, qc = lane & 3;
    const int rb = wm * 32 + qr;
    const int cb = wn * 40 + 2 * qc;

    uint32_t xs_b = (uint32_t)__cvta_generic_to_shared(xbuf);
    int rowA = wm * 32 + ((lane >> 3) & 1) * 8 + (lane & 7);
    uint32_t xaddr0 = xs_b + (uint32_t)((rowA * XS + (lane >> 4) * 4) * 4);

    #pragma unroll 1
    for (int pass = 0; pass < 2; pass++) {
        const int slice = 3 + pass;            // 3: w1_a -> PV[0:160], 4: wt_a -> PV[160:320]
        const int coloff = pass ? 160 : 0;
        float acc[2][5][4] = {};
        gemm_pass2(acc, g_WPK + (slice * 4 + wn) * 6400, xaddr0, lane);
        #pragma unroll
        for (int mf = 0; mf < 2; mf++) {
            int r = rb + mf * 16;
            int vA = v0 + r, vB = v0 + r + 8;
            #pragma unroll
            for (int nf = 0; nf < 5; nf++) {
                int c = cb + nf * 8;
                if (vA < N_VEH)
                    *(float2*)(g_PV + (size_t)vA * 320 + coloff + c) =
                        make_float2(acc[mf][nf][0], acc[mf][nf][1]);
                if (vB < N_VEH)
                    *(float2*)(g_PV + (size_t)vB * 320 + coloff + c) =
                        make_float2(acc[mf][nf][2], acc[mf][nf][3]);
            }
        }
    }
}

// Kernel 2: fused per-path pipeline
__global__ void __launch_bounds__(NTHREADS, 1)
path_main_kernel(
    const float* __restrict__ paths, const float* __restrict__ Z_pat,
    const int* __restrict__ u,
    const float* __restrict__ g1w, const float* __restrict__ g1b,
    const float* __restrict__ g2w, const float* __restrict__ g2b,
    const float* __restrict__ wh, const float* __restrict__ bh,
    float* __restrict__ out)
{
    extern __shared__ float sm[];
    float* xbuf = sm;                         // 128*164  (xp, later h1r)
    float* tbuf = xbuf + TILE_M * XS;         // 128*164  (skip branch t)
    int*   u_s  = (int*)(tbuf + TILE_M * XS); // 128
    float* rsum = (float*)(u_s + 128);        // 128
    float* rssq = rsum + 128;                 // 128
    float* oacc = rssq + 128;                 // 128
    float* p1w = oacc + 128;                  // 5 x 160 params
    float* p1b = p1w + 160;
    float* p2w = p1b + 160;
    float* p2b = p2w + 160;
    float* pwh = p2b + 160;

    const int tid = threadIdx.x;
    const int row0 = blockIdx.x * TILE_M;

    for (int i = tid; i < 160; i += NTHREADS) {
        p1w[i] = g1w[i]; p1b[i] = g1b[i];
        p2w[i] = g2w[i]; p2b[i] = g2b[i];
        pwh[i] = wh[i];
    }
    if (tid < 128) {
        u_s[tid] = u[row0 + tid];
        rsum[tid] = 0.0f; rssq[tid] = 0.0f; oacc[tid] = 0.0f;
    }
    for (int idx = tid; idx < TILE_M * 160; idx += NTHREADS) {
        int r = idx / 160, c = idx - r * 160;
        float v = (c < 128) ? paths[(size_t)(row0 + r) * 128 + c]
                            : Z_pat[(size_t)(row0 + r) * 32 + (c - 128)];
        xbuf[r * XS + c] = __uint_as_float(tf32u(v));
    }
    __syncthreads();

    const int lane = tid & 31, warp = tid >> 5;
    const int wm = warp & 3, wn = warp >> 2;
    const int qr = lane >> 2, qc = lane & 3;
    const int rb = wm * 32 + qr;
    const int cb = wn * 40 + 2 * qc;

    uint32_t xs_b = (uint32_t)__cvta_generic_to_shared(xbuf);
    int rowA = wm * 32 + ((lane >> 3) & 1) * 8 + (lane & 7);
    uint32_t xaddr0 = xs_b + (uint32_t)((rowA * XS + (lane >> 4) * 4) * 4);

    // ---- pass T: t = xp @ wt_p^T + PV[u][160:320] -> tbuf ----
    {
        float acc[2][5][4] = {};
        gemm_pass2(acc, g_WPK + (1 * 4 + wn) * 6400, xaddr0, lane);
        #pragma unroll
        for (int mf = 0; mf < 2; mf++) {
            int r = rb + mf * 16;
            const float* pv0 = g_PV + (size_t)u_s[r] * 320 + 160 + cb;
            const float* pv1 = g_PV + (size_t)u_s[r + 8] * 320 + 160 + cb;
            #pragma unroll
            for (int nf = 0; nf < 5; nf++) {
                float2 v0 = *(const float2*)(pv0 + nf * 8);
                float2 v1 = *(const float2*)(pv1 + nf * 8);
                *(float2*)(tbuf + r * XS + cb + nf * 8) =
                    make_float2(acc[mf][nf][0] + v0.x, acc[mf][nf][1] + v0.y);
                *(float2*)(tbuf + (r + 8) * XS + cb + nf * 8) =
                    make_float2(acc[mf][nf][2] + v1.x, acc[mf][nf][3] + v1.y);
            }
        }
    }

    // ---- pass 1: h1 = xp @ w1_p^T + PV[u][0:160], GN1, ReLU -> xbuf ----
    {
        float acc[2][5][4] = {};
        gemm_pass2(acc, g_WPK + (0 * 4 + wn) * 6400, xaddr0, lane);
        #pragma unroll
        for (int mf = 0; mf < 2; mf++) {
            int r = rb + mf * 16;
            const float* pv0 = g_PV + (size_t)u_s[r] * 320 + cb;
            const float* pv1 = g_PV + (size_t)u_s[r + 8] * 320 + cb;
            #pragma unroll
            for (int nf = 0; nf < 5; nf++) {
                float2 v0 = *(const float2*)(pv0 + nf * 8);
                float2 v1 = *(const float2*)(pv1 + nf * 8);
                acc[mf][nf][0] += v0.x; acc[mf][nf][1] += v0.y;
                acc[mf][nf][2] += v1.x; acc[mf][nf][3] += v1.y;
            }
        }
        // GN1 stats
        #pragma unroll
        for (int mf = 0; mf < 2; mf++)
            #pragma unroll
            for (int h = 0; h < 2; h++) {
                float s = 0.0f, ss = 0.0f;
                #pragma unroll
                for (int nf = 0; nf < 5; nf++) {
                    float a0 = acc[mf][nf][2 * h], a1 = acc[mf][nf][2 * h + 1];
                    s += a0 + a1; ss += a0 * a0 + a1 * a1;
                }
                s  += __shfl_xor_sync(0xffffffffu, s, 1);
                ss += __shfl_xor_sync(0xffffffffu, ss, 1);
                s  += __shfl_xor_sync(0xffffffffu, s, 2);
                ss += __shfl_xor_sync(0xffffffffu, ss, 2);
                if (qc == 0) {
                    int r = rb + mf * 16 + 8 * h;
                    atomicAdd(&rsum[r], s);
                    atomicAdd(&rssq[r], ss);
                }
            }
        __syncthreads();
        // normalize + relu, overwrite xbuf with h1r (tf32-rounded)
        #pragma unroll
        for (int mf = 0; mf < 2; mf++)
            #pragma unroll
            for (int h = 0; h < 2; h++) {
                int r = rb + mf * 16 + 8 * h;
                float mean = rsum[r] * (1.0f / 160.0f);
                float var  = rssq[r] * (1.0f / 160.0f) - mean * mean;
                float rstd = rsqrtf(var + 1e-5f);
                #pragma unroll
                for (int nf = 0; nf < 5; nf++)
                    #pragma unroll
                    for (int e = 0; e < 2; e++) {
                        int col = cb + nf * 8 + e;
                        float v = (acc[mf][nf][2 * h + e] - mean) * rstd * p1w[col] + p1b[col];
                        v = fmaxf(v, 0.0f);
                        xbuf[r * XS + col] = __uint_as_float(tf32u(v));
                    }
            }
    }
    __syncthreads();
    if (tid < 128) { rsum[tid] = 0.0f; rssq[tid] = 0.0f; }
    __syncthreads();   // make resets visible before pass-2 stats atomics

    // ---- pass 2: h2 = h1r @ w2^T, GN2, +t, ReLU, head ----
    {
        float acc[2][5][4] = {};
        gemm_pass2(acc, g_WPK + (2 * 4 + wn) * 6400, xaddr0, lane);
        #pragma unroll
        for (int mf = 0; mf < 2; mf++)
            #pragma unroll
            for (int h = 0; h < 2; h++) {
                float s = 0.0f, ss = 0.0f;
                #pragma unroll
                for (int nf = 0; nf < 5; nf++) {
                    float a0 = acc[mf][nf][2 * h], a1 = acc[mf][nf][2 * h + 1];
                    s += a0 + a1; ss += a0 * a0 + a1 * a1;
                }
                s  += __shfl_xor_sync(0xffffffffu, s, 1);
                ss += __shfl_xor_sync(0xffffffffu, ss, 1);
                s  += __shfl_xor_sync(0xffffffffu, s, 2);
                ss += __shfl_xor_sync(0xffffffffu, ss, 2);
                if (qc == 0) {
                    int r = rb + mf * 16 + 8 * h;
                    atomicAdd(&rsum[r], s);
                    atomicAdd(&rssq[r], ss);
                }
            }
        __syncthreads();
        #pragma unroll
        for (int mf = 0; mf < 2; mf++)
            #pragma unroll
            for (int h = 0; h < 2; h++) {
                int r = rb + mf * 16 + 8 * h;
                float mean = rsum[r] * (1.0f / 160.0f);
                float var  = rssq[r] * (1.0f / 160.0f) - mean * mean;
                float rstd = rsqrtf(var + 1e-5f);
                float part = 0.0f;
                #pragma unroll
                for (int nf = 0; nf < 5; nf++) {
                    float2 tv = *(const float2*)(tbuf + r * XS + cb + nf * 8);
                    int col = cb + nf * 8;
                    float v0 = (acc[mf][nf][2 * h]     - mean) * rstd * p2w[col]     + p2b[col]     + tv.x;
                    float v1 = (acc[mf][nf][2 * h + 1] - mean) * rstd * p2w[col + 1] + p2b[col + 1] + tv.y;
                    v0 = fmaxf(v0, 0.0f);
                    v1 = fmaxf(v1, 0.0f);
                    part += v0 * pwh[col] + v1 * pwh[col + 1];
                }
                part += __shfl_xor_sync(0xffffffffu, part, 1);
                part += __shfl_xor_sync(0xffffffffu, part, 2);
                if (qc == 0) atomicAdd(&oacc[r], part);
            }
    }
    __syncthreads();
    if (tid < 128) out[row0 + tid] = oacc[tid] + bh[0];
}

extern "C" void kernel_launch(void* const* d_in, const int* in_sizes, int n_in,
                              void* d_out, int out_size)
{
    const float* actors = (const float*)d_in[0];
    const float* paths  = (const float*)d_in[1];
    const float* Z_act  = (const float*)d_in[2];
    const float* Z_pat  = (const float*)d_in[3];
    const int*   u      = (const int*)  d_in[4];
    const float* w1     = (const float*)d_in[5];
    const float* w2     = (const float*)d_in[6];
    const float* wt     = (const float*)d_in[7];
    const float* g1w    = (const float*)d_in[8];
    const float* g1b    = (const float*)d_in[9];
    const float* g2w    = (const float*)d_in[10];
    const float* g2b    = (const float*)d_in[11];
    const float* wh     = (const float*)d_in[12];
    const float* bh     = (const float*)d_in[13];
    float* out = (float*)d_out;

    const int smem1 = TILE_M * XS * 4;
    const int smem2 = 2 * TILE_M * XS * 4 + 4 * 128 * 4 + 5 * 160 * 4;

    cudaFuncSetAttribute(veh_pre_kernel,   cudaFuncAttributeMaxDynamicSharedMemorySize, smem1);
    cudaFuncSetAttribute(path_main_kernel, cudaFuncAttributeMaxDynamicSharedMemorySize, smem2);

    pack_kernel<<<(5 * 25600 + 255) / 256, 256>>>(w1, w2, wt);
    veh_pre_kernel<<<(N_VEH + TILE_M - 1) / TILE_M, NTHREADS, smem1>>>(actors, Z_act);
    path_main_kernel<<<N_PATHS / TILE_M, NTHREADS, smem2>>>(
        paths, Z_pat, u, g1w, g1b, g2w, g2b, wh, bh, out);
}

// round 7
// speedup vs baseline: 1.9117x; 1.4196x over previous
#include <cuda_runtime.h>
#include <cuda_fp16.h>
#include <cstdint>

#define N_VEH    40000
#define N_PATHS  400000
#define TILE_M   128
#define NTHREADS 512
#define XSB      336     // xbuf row stride in BYTES (168 halfs); 84 words %32 = 20 -> conflict-free ldmatrix
#define XS       164     // tbuf row stride in floats

// Per-vehicle partials [N_VEH][320]: cols 0..159 = w1_a @ va, 160..319 = wt_a @ va
__device__ float g_PV[(size_t)N_VEH * 320];
// Packed fp16 weights in m16n8k16 B-fragment order:
// [slice:5][wn:4][chunk:10][nf:5][lane:32] of uint2 {b0,b1}
// slice 0: w1[:,0:160], 1: wt[:,0:160], 2: w2, 3: w1[:,160:320], 4: wt[:,160:320]
__device__ __align__(16) uint2 g_WPK[32000];

__device__ __forceinline__ unsigned h2u(float lo, float hi) {
    __half2 h = __floats2half2_rn(lo, hi);
    return *(unsigned*)&h;
}

__device__ __forceinline__ void mma16(float* d, const unsigned* a, const unsigned* b) {
    asm volatile(
        "mma.sync.aligned.m16n8k16.row.col.f32.f16.f16.f32 "
        "{%0,%1,%2,%3}, {%4,%5,%6,%7}, {%8,%9}, {%0,%1,%2,%3};\n"
        : "+f"(d[0]), "+f"(d[1]), "+f"(d[2]), "+f"(d[3])
        : "r"(a[0]), "r"(a[1]), "r"(a[2]), "r"(a[3]), "r"(b[0]), "r"(b[1]));
}
__device__ __forceinline__ void ldsm4(unsigned a[4], uint32_t addr) {
    asm volatile("ldmatrix.sync.aligned.m8n8.x4.shared.b16 {%0,%1,%2,%3}, [%4];"
                 : "=r"(a[0]), "=r"(a[1]), "=r"(a[2]), "=r"(a[3]) : "r"(addr));
}

// Pack kernel: fp16 B fragments. One thread per uint2.
__global__ void pack_kernel(const float* __restrict__ w1, const float* __restrict__ w2,
                            const float* __restrict__ wt)
{
    int idx = blockIdx.x * blockDim.x + threadIdx.x;
    if (idx >= 32000) return;
    int lane = idx & 31;
    int nf   = (idx >> 5) % 5;
    int chunk= (idx / 160) % 10;
    int wn   = (idx / 1600) & 3;
    int slice= idx / 6400;

    const float* src; int gs, ko;
    switch (slice) {
        case 0: src = w1; gs = 320; ko = 0;   break;
        case 1: src = wt; gs = 320; ko = 0;   break;
        case 2: src = w2; gs = 160; ko = 0;   break;
        case 3: src = w1; gs = 320; ko = 160; break;
        default:src = wt; gs = 320; ko = 160; break;
    }
    int n = wn * 40 + nf * 8 + (lane >> 2);
    int kb = chunk * 16 + (lane & 3) * 2;
    const float* r = src + (size_t)n * gs + ko;
    uint2 o;
    o.x = h2u(r[kb],     r[kb + 1]);
    o.y = h2u(r[kb + 8], r[kb + 9]);
    g_WPK[idx] = o;
}

// GEMM pass: acc[2][5][4] += X(128x160 fp16 in smem) @ Wslice^T (fp16), fp32 accum.
// 16 warps = 4(m) x 4(n); warp tile 32 rows x 40 cols. K chunks of 16, A+B double-buffered.
__device__ __forceinline__ void gemm_pass_h(
    float acc[2][5][4],
    const uint2* __restrict__ pk,     // g_WPK + (slice*4+wn)*1600
    uint32_t xaddr0, int lane)
{
    const uint2* bp = pk + lane;
    uint2 b[2][5];
    unsigned a[2][2][4];
    #pragma unroll
    for (int j = 0; j < 5; j++) b[0][j] = __ldg(bp + j * 32);
    ldsm4(a[0][0], xaddr0);
    ldsm4(a[0][1], xaddr0 + 16 * XSB);

    #pragma unroll
    for (int chunk = 0; chunk < 10; chunk++) {
        const int cur = chunk & 1;
        if (chunk < 9) {
            #pragma unroll
            for (int j = 0; j < 5; j++)
                b[cur ^ 1][j] = __ldg(bp + ((chunk + 1) * 5 + j) * 32);
            uint32_t ad = xaddr0 + (uint32_t)((chunk + 1) * 32);
            ldsm4(a[cur ^ 1][0], ad);
            ldsm4(a[cur ^ 1][1], ad + 16 * XSB);
        }
        #pragma unroll
        for (int mf = 0; mf < 2; mf++)
            #pragma unroll
            for (int nf = 0; nf < 5; nf++)
                mma16(acc[mf][nf], a[cur][mf], &b[cur][nf].x);
    }
}

// Kernel 1: per-vehicle partial sums into g_PV (slices 3,4)
__global__ void __launch_bounds__(NTHREADS, 1)
veh_pre_kernel(const float* __restrict__ actors, const float* __restrict__ Z_act)
{
    extern __shared__ char smem[];
    char* xbuf = smem;                       // 128 * 336 bytes (fp16)
    const int tid = threadIdx.x;
    const int v0 = blockIdx.x * TILE_M;

    for (int i = tid; i < TILE_M * 40; i += NTHREADS) {
        int r = i / 40, k4 = i - r * 40;
        int v = v0 + r;
        float4 x = make_float4(0.f, 0.f, 0.f, 0.f);
        if (v < N_VEH)
            x = (k4 < 32) ? __ldg((const float4*)actors + (size_t)v * 32 + k4)
                          : __ldg((const float4*)Z_act + (size_t)v * 8 + (k4 - 32));
        uint2 o; o.x = h2u(x.x, x.y); o.y = h2u(x.z, x.w);
        *(uint2*)(xbuf + r * XSB + k4 * 8) = o;
    }
    __syncthreads();

    const int lane = tid & 31, warp = tid >> 5;
    const int wm = warp & 3, wn = warp >> 2;
    const int qr = lane >> 2, qc = lane & 3;
    const int rb = wm * 32 + qr;
    const int cb = wn * 40 + 2 * qc;

    uint32_t xs_b = (uint32_t)__cvta_generic_to_shared(xbuf);
    uint32_t xaddr0 = xs_b + (uint32_t)((wm * 32 + (lane & 15)) * XSB + (lane >> 4) * 16);

    #pragma unroll 1
    for (int pass = 0; pass < 2; pass++) {
        const int slice = 3 + pass;
        const int coloff = pass ? 160 : 0;
        float acc[2][5][4] = {};
        gemm_pass_h(acc, g_WPK + (slice * 4 + wn) * 1600, xaddr0, lane);
        #pragma unroll
        for (int mf = 0; mf < 2; mf++) {
            int r = rb + mf * 16;
            int vA = v0 + r, vB = v0 + r + 8;
            #pragma unroll
            for (int nf = 0; nf < 5; nf++) {
                int c = cb + nf * 8;
                if (vA < N_VEH)
                    *(float2*)(g_PV + (size_t)vA * 320 + coloff + c) =
                        make_float2(acc[mf][nf][0], acc[mf][nf][1]);
                if (vB < N_VEH)
                    *(float2*)(g_PV + (size_t)vB * 320 + coloff + c) =
                        make_float2(acc[mf][nf][2], acc[mf][nf][3]);
            }
        }
    }
}

// Kernel 2: fused per-path pipeline
__global__ void __launch_bounds__(NTHREADS, 1)
path_main_kernel(
    const float* __restrict__ paths, const float* __restrict__ Z_pat,
    const int* __restrict__ u,
    const float* __restrict__ g1w, const float* __restrict__ g1b,
    const float* __restrict__ g2w, const float* __restrict__ g2b,
    const float* __restrict__ wh, const float* __restrict__ bh,
    float* __restrict__ out)
{
    extern __shared__ char smem[];
    char*  xbuf = smem;                        // 128*336 B fp16 (xp, later h1r)
    float* tbuf = (float*)(smem + TILE_M * XSB);        // 128*164 f32 skip branch
    int*   u_s  = (int*)(tbuf + TILE_M * XS);  // 128
    float* rsum = (float*)(u_s + 128);         // 128
    float* rssq = rsum + 128;                  // 128
    float* oacc = rssq + 128;                  // 128
    float* p1w = oacc + 128;                   // 5 x 160 params
    float* p1b = p1w + 160;
    float* p2w = p1b + 160;
    float* p2b = p2w + 160;
    float* pwh = p2b + 160;

    const int tid = threadIdx.x;
    const int row0 = blockIdx.x * TILE_M;

    for (int i = tid; i < 160; i += NTHREADS) {
        p1w[i] = g1w[i]; p1b[i] = g1b[i];
        p2w[i] = g2w[i]; p2b[i] = g2b[i];
        pwh[i] = wh[i];
    }
    if (tid < 128) {
        u_s[tid] = u[row0 + tid];
        rsum[tid] = 0.0f; rssq[tid] = 0.0f; oacc[tid] = 0.0f;
    }
    for (int i = tid; i < TILE_M * 40; i += NTHREADS) {
        int r = i / 40, k4 = i - r * 40;
        float4 x = (k4 < 32) ? __ldg((const float4*)paths + (size_t)(row0 + r) * 32 + k4)
                             : __ldg((const float4*)Z_pat + (size_t)(row0 + r) * 8 + (k4 - 32));
        uint2 o; o.x = h2u(x.x, x.y); o.y = h2u(x.z, x.w);
        *(uint2*)(xbuf + r * XSB + k4 * 8) = o;
    }
    __syncthreads();

    const int lane = tid & 31, warp = tid >> 5;
    const int wm = warp & 3, wn = warp >> 2;
    const int qr = lane >> 2, qc = lane & 3;
    const int rb = wm * 32 + qr;
    const int cb = wn * 40 + 2 * qc;

    uint32_t xs_b = (uint32_t)__cvta_generic_to_shared(xbuf);
    uint32_t xaddr0 = xs_b + (uint32_t)((wm * 32 + (lane & 15)) * XSB + (lane >> 4) * 16);

    // ---- pass T: t = xp @ wt_p^T + PV[u][160:320] -> tbuf ----
    {
        float acc[2][5][4] = {};
        gemm_pass_h(acc, g_WPK + (1 * 4 + wn) * 1600, xaddr0, lane);
        #pragma unroll
        for (int mf = 0; mf < 2; mf++) {
            int r = rb + mf * 16;
            const float* pv0 = g_PV + (size_t)u_s[r] * 320 + 160 + cb;
            const float* pv1 = g_PV + (size_t)u_s[r + 8] * 320 + 160 + cb;
            #pragma unroll
            for (int nf = 0; nf < 5; nf++) {
                float2 v0 = *(const float2*)(pv0 + nf * 8);
                float2 v1 = *(const float2*)(pv1 + nf * 8);
                *(float2*)(tbuf + r * XS + cb + nf * 8) =
                    make_float2(acc[mf][nf][0] + v0.x, acc[mf][nf][1] + v0.y);
                *(float2*)(tbuf + (r + 8) * XS + cb + nf * 8) =
                    make_float2(acc[mf][nf][2] + v1.x, acc[mf][nf][3] + v1.y);
            }
        }
    }

    // ---- pass 1: h1 = xp @ w1_p^T + PV[u][0:160], GN1, ReLU -> xbuf (fp16) ----
    {
        float acc[2][5][4] = {};
        gemm_pass_h(acc, g_WPK + (0 * 4 + wn) * 1600, xaddr0, lane);
        #pragma unroll
        for (int mf = 0; mf < 2; mf++) {
            int r = rb + mf * 16;
            const float* pv0 = g_PV + (size_t)u_s[r] * 320 + cb;
            const float* pv1 = g_PV + (size_t)u_s[r + 8] * 320 + cb;
            #pragma unroll
            for (int nf = 0; nf < 5; nf++) {
                float2 v0 = *(const float2*)(pv0 + nf * 8);
                float2 v1 = *(const float2*)(pv1 + nf * 8);
                acc[mf][nf][0] += v0.x; acc[mf][nf][1] += v0.y;
                acc[mf][nf][2] += v1.x; acc[mf][nf][3] += v1.y;
            }
        }
        #pragma unroll
        for (int mf = 0; mf < 2; mf++)
            #pragma unroll
            for (int h = 0; h < 2; h++) {
                float s = 0.0f, ss = 0.0f;
                #pragma unroll
                for (int nf = 0; nf < 5; nf++) {
                    float a0 = acc[mf][nf][2 * h], a1 = acc[mf][nf][2 * h + 1];
                    s += a0 + a1; ss += a0 * a0 + a1 * a1;
                }
                s  += __shfl_xor_sync(0xffffffffu, s, 1);
                ss += __shfl_xor_sync(0xffffffffu, ss, 1);
                s  += __shfl_xor_sync(0xffffffffu, s, 2);
                ss += __shfl_xor_sync(0xffffffffu, ss, 2);
                if (qc == 0) {
                    int r = rb + mf * 16 + 8 * h;
                    atomicAdd(&rsum[r], s);
                    atomicAdd(&rssq[r], ss);
                }
            }
        __syncthreads();
        #pragma unroll
        for (int mf = 0; mf < 2; mf++)
            #pragma unroll
            for (int h = 0; h < 2; h++) {
                int r = rb + mf * 16 + 8 * h;
                float mean = rsum[r] * (1.0f / 160.0f);
                float var  = rssq[r] * (1.0f / 160.0f) - mean * mean;
                float rstd = rsqrtf(var + 1e-5f);
                #pragma unroll
                for (int nf = 0; nf < 5; nf++) {
                    int col = cb + nf * 8;
                    float v0 = fmaxf((acc[mf][nf][2 * h]     - mean) * rstd * p1w[col]     + p1b[col],     0.f);
                    float v1 = fmaxf((acc[mf][nf][2 * h + 1] - mean) * rstd * p1w[col + 1] + p1b[col + 1], 0.f);
                    *(unsigned*)(xbuf + r * XSB + col * 2) = h2u(v0, v1);
                }
            }
    }
    __syncthreads();
    if (tid < 128) { rsum[tid] = 0.0f; rssq[tid] = 0.0f; }
    __syncthreads();

    // ---- pass 2: h2 = h1r @ w2^T, GN2, +t, ReLU, head ----
    {
        float acc[2][5][4] = {};
        gemm_pass_h(acc, g_WPK + (2 * 4 + wn) * 1600, xaddr0, lane);
        #pragma unroll
        for (int mf = 0; mf < 2; mf++)
            #pragma unroll
            for (int h = 0; h < 2; h++) {
                float s = 0.0f, ss = 0.0f;
                #pragma unroll
                for (int nf = 0; nf < 5; nf++) {
                    float a0 = acc[mf][nf][2 * h], a1 = acc[mf][nf][2 * h + 1];
                    s += a0 + a1; ss += a0 * a0 + a1 * a1;
                }
                s  += __shfl_xor_sync(0xffffffffu, s, 1);
                ss += __shfl_xor_sync(0xffffffffu, ss, 1);
                s  += __shfl_xor_sync(0xffffffffu, s, 2);
                ss += __shfl_xor_sync(0xffffffffu, ss, 2);
                if (qc == 0) {
                    int r = rb + mf * 16 + 8 * h;
                    atomicAdd(&rsum[r], s);
                    atomicAdd(&rssq[r], ss);
                }
            }
        __syncthreads();
        #pragma unroll
        for (int mf = 0; mf < 2; mf++)
            #pragma unroll
            for (int h = 0; h < 2; h++) {
                int r = rb + mf * 16 + 8 * h;
                float mean = rsum[r] * (1.0f / 160.0f);
                float var  = rssq[r] * (1.0f / 160.0f) - mean * mean;
                float rstd = rsqrtf(var + 1e-5f);
                float part = 0.0f;
                #pragma unroll
                for (int nf = 0; nf < 5; nf++) {
                    float2 tv = *(const float2*)(tbuf + r * XS + cb + nf * 8);
                    int col = cb + nf * 8;
                    float v0 = (acc[mf][nf][2 * h]     - mean) * rstd * p2w[col]     + p2b[col]     + tv.x;
                    float v1 = (acc[mf][nf][2 * h + 1] - mean) * rstd * p2w[col + 1] + p2b[col + 1] + tv.y;
                    v0 = fmaxf(v0, 0.0f);
                    v1 = fmaxf(v1, 0.0f);
                    part += v0 * pwh[col] + v1 * pwh[col + 1];
                }
                part += __shfl_xor_sync(0xffffffffu, part, 1);
                part += __shfl_xor_sync(0xffffffffu, part, 2);
                if (qc == 0) atomicAdd(&oacc[r], part);
            }
    }
    __syncthreads();
    if (tid < 128) out[row0 + tid] = oacc[tid] + bh[0];
}

extern "C" void kernel_launch(void* const* d_in, const int* in_sizes, int n_in,
                              void* d_out, int out_size)
{
    const float* actors = (const float*)d_in[0];
    const float* paths  = (const float*)d_in[1];
    const float* Z_act  = (const float*)d_in[2];
    const float* Z_pat  = (const float*)d_in[3];
    const int*   u      = (const int*)  d_in[4];
    const float* w1     = (const float*)d_in[5];
    const float* w2     = (const float*)d_in[6];
    const float* wt     = (const float*)d_in[7];
    const float* g1w    = (const float*)d_in[8];
    const float* g1b    = (const float*)d_in[9];
    const float* g2w    = (const float*)d_in[10];
    const float* g2b    = (const float*)d_in[11];
    const float* wh     = (const float*)d_in[12];
    const float* bh     = (const float*)d_in[13];
    float* out = (float*)d_out;

    const int smem1 = TILE_M * XSB;
    const int smem2 = TILE_M * XSB + TILE_M * XS * 4 + 4 * 128 * 4 + 5 * 160 * 4;

    cudaFuncSetAttribute(veh_pre_kernel,   cudaFuncAttributeMaxDynamicSharedMemorySize, smem1);
    cudaFuncSetAttribute(path_main_kernel, cudaFuncAttributeMaxDynamicSharedMemorySize, smem2);

    pack_kernel<<<(32000 + 255) / 256, 256>>>(w1, w2, wt);
    veh_pre_kernel<<<(N_VEH + TILE_M - 1) / TILE_M, NTHREADS, smem1>>>(actors, Z_act);
    path_main_kernel<<<N_PATHS / TILE_M, NTHREADS, smem2>>>(
        paths, Z_pat, u, g1w, g1b, g2w, g2b, wh, bh, out);
}

// round 8
// speedup vs baseline: 1.9961x; 1.0442x over previous
#include <cuda_runtime.h>
#include <cuda_fp16.h>
#include <cstdint>

#define N_VEH    40000
#define N_PATHS  400000
#define TILE_M   64
#define NTHREADS 256
#define VTILE    128
#define VTHREADS 512
#define XSB      336     // xbuf row stride in BYTES (168 halfs); conflict-free ldmatrix

// Per-vehicle partials [N_VEH][320]: cols 0..159 = w1_a @ va, 160..319 = wt_a @ va
__device__ float g_PV[(size_t)N_VEH * 320];
// Packed fp16 weights in m16n8k16 B-fragment order:
// [slice:5][wn:4][chunk:10][nf:5][lane:32] of uint2 {b0,b1}
// slice 0: w1[:,0:160], 1: wt[:,0:160], 2: w2, 3: w1[:,160:320], 4: wt[:,160:320]
__device__ __align__(16) uint2 g_WPK[32000];

__device__ __forceinline__ unsigned h2u(float lo, float hi) {
    __half2 h = __floats2half2_rn(lo, hi);
    return *(unsigned*)&h;
}

__device__ __forceinline__ void mma16(float* d, const unsigned* a, const unsigned* b) {
    asm volatile(
        "mma.sync.aligned.m16n8k16.row.col.f32.f16.f16.f32 "
        "{%0,%1,%2,%3}, {%4,%5,%6,%7}, {%8,%9}, {%0,%1,%2,%3};\n"
        : "+f"(d[0]), "+f"(d[1]), "+f"(d[2]), "+f"(d[3])
        : "r"(a[0]), "r"(a[1]), "r"(a[2]), "r"(a[3]), "r"(b[0]), "r"(b[1]));
}
__device__ __forceinline__ void ldsm4(unsigned a[4], uint32_t addr) {
    asm volatile("ldmatrix.sync.aligned.m8n8.x4.shared.b16 {%0,%1,%2,%3}, [%4];"
                 : "=r"(a[0]), "=r"(a[1]), "=r"(a[2]), "=r"(a[3]) : "r"(addr));
}

// Pack kernel: fp16 B fragments. One thread per uint2.
__global__ void pack_kernel(const float* __restrict__ w1, const float* __restrict__ w2,
                            const float* __restrict__ wt)
{
    int idx = blockIdx.x * blockDim.x + threadIdx.x;
    if (idx >= 32000) return;
    int lane = idx & 31;
    int nf   = (idx >> 5) % 5;
    int chunk= (idx / 160) % 10;
    int wn   = (idx / 1600) & 3;
    int slice= idx / 6400;

    const float* src; int gs, ko;
    switch (slice) {
        case 0: src = w1; gs = 320; ko = 0;   break;
        case 1: src = wt; gs = 320; ko = 0;   break;
        case 2: src = w2; gs = 160; ko = 0;   break;
        case 3: src = w1; gs = 320; ko = 160; break;
        default:src = wt; gs = 320; ko = 160; break;
    }
    int n = wn * 40 + nf * 8 + (lane >> 2);
    int kb = chunk * 16 + (lane & 3) * 2;
    const float* r = src + (size_t)n * gs + ko;
    uint2 o;
    o.x = h2u(r[kb],     r[kb + 1]);
    o.y = h2u(r[kb + 8], r[kb + 9]);
    g_WPK[idx] = o;
}

// GEMM pass: acc[2][5][4] += X(rows x 160 fp16 in smem) @ Wslice^T, fp32 accum.
// Warp tile 32 rows x 40 cols. K chunks of 16; B double-buffered, A single.
__device__ __forceinline__ void gemm_pass_h(
    float acc[2][5][4],
    const uint2* __restrict__ pk,     // g_WPK + (slice*4+wn)*1600
    uint32_t xaddr0, int lane)
{
    const uint2* bp = pk + lane;
    uint2 b[2][5];
    #pragma unroll
    for (int j = 0; j < 5; j++) b[0][j] = __ldg(bp + j * 32);

    #pragma unroll
    for (int chunk = 0; chunk < 10; chunk++) {
        const int cur = chunk & 1;
        if (chunk < 9) {
            #pragma unroll
            for (int j = 0; j < 5; j++)
                b[cur ^ 1][j] = __ldg(bp + ((chunk + 1) * 5 + j) * 32);
        }
        unsigned a[2][4];
        uint32_t ad = xaddr0 + (uint32_t)(chunk * 32);
        ldsm4(a[0], ad);
        ldsm4(a[1], ad + 16 * XSB);
        #pragma unroll
        for (int mf = 0; mf < 2; mf++)
            #pragma unroll
            for (int nf = 0; nf < 5; nf++)
                mma16(acc[mf][nf], a[mf], &b[cur][nf].x);
    }
}

// Kernel 1: per-vehicle partial sums into g_PV (slices 3,4). 512 thr, 128-row tile.
__global__ void __launch_bounds__(VTHREADS, 1)
veh_pre_kernel(const float* __restrict__ actors, const float* __restrict__ Z_act)
{
    extern __shared__ char smem[];
    char* xbuf = smem;                       // 128 * 336 bytes (fp16)
    const int tid = threadIdx.x;
    const int v0 = blockIdx.x * VTILE;

    for (int i = tid; i < VTILE * 40; i += VTHREADS) {
        int r = i / 40, k4 = i - r * 40;
        int v = v0 + r;
        float4 x = make_float4(0.f, 0.f, 0.f, 0.f);
        if (v < N_VEH)
            x = (k4 < 32) ? __ldg((const float4*)actors + (size_t)v * 32 + k4)
                          : __ldg((const float4*)Z_act + (size_t)v * 8 + (k4 - 32));
        uint2 o; o.x = h2u(x.x, x.y); o.y = h2u(x.z, x.w);
        *(uint2*)(xbuf + r * XSB + k4 * 8) = o;
    }
    __syncthreads();

    const int lane = tid & 31, warp = tid >> 5;
    const int wm = warp & 3, wn = warp >> 2;
    const int qr = lane >> 2, qc = lane & 3;
    const int rb = wm * 32 + qr;
    const int cb = wn * 40 + 2 * qc;

    uint32_t xs_b = (uint32_t)__cvta_generic_to_shared(xbuf);
    uint32_t xaddr0 = xs_b + (uint32_t)((wm * 32 + (lane & 15)) * XSB + (lane >> 4) * 16);

    #pragma unroll 1
    for (int pass = 0; pass < 2; pass++) {
        const int slice = 3 + pass;
        const int coloff = pass ? 160 : 0;
        float acc[2][5][4] = {};
        gemm_pass_h(acc, g_WPK + (slice * 4 + wn) * 1600, xaddr0, lane);
        #pragma unroll
        for (int mf = 0; mf < 2; mf++) {
            int r = rb + mf * 16;
            int vA = v0 + r, vB = v0 + r + 8;
            #pragma unroll
            for (int nf = 0; nf < 5; nf++) {
                int c = cb + nf * 8;
                if (vA < N_VEH)
                    *(float2*)(g_PV + (size_t)vA * 320 + coloff + c) =
                        make_float2(acc[mf][nf][0], acc[mf][nf][1]);
                if (vB < N_VEH)
                    *(float2*)(g_PV + (size_t)vB * 320 + coloff + c) =
                        make_float2(acc[mf][nf][2], acc[mf][nf][3]);
            }
        }
    }
}

// Kernel 2: fused per-path pipeline. 256 thr, 64-row tile, 2 CTAs/SM, t in regs.
__global__ void __launch_bounds__(NTHREADS, 2)
path_main_kernel(
    const float* __restrict__ paths, const float* __restrict__ Z_pat,
    const int* __restrict__ u,
    const float* __restrict__ g1w, const float* __restrict__ g1b,
    const float* __restrict__ g2w, const float* __restrict__ g2b,
    const float* __restrict__ wh, const float* __restrict__ bh,
    float* __restrict__ out)
{
    extern __shared__ char smem[];
    char*  xbuf = smem;                            // 64*336 B fp16 (xp, later h1r)
    int*   u_s  = (int*)(smem + TILE_M * XSB);     // 64
    float* rsum = (float*)(u_s + TILE_M);          // 64
    float* rssq = rsum + TILE_M;                   // 64
    float* oacc = rssq + TILE_M;                   // 64
    float* p1w = oacc + TILE_M;                    // 5 x 160 params
    float* p1b = p1w + 160;
    float* p2w = p1b + 160;
    float* p2b = p2w + 160;
    float* pwh = p2b + 160;

    const int tid = threadIdx.x;
    const int row0 = blockIdx.x * TILE_M;

    for (int i = tid; i < 160; i += NTHREADS) {
        p1w[i] = g1w[i]; p1b[i] = g1b[i];
        p2w[i] = g2w[i]; p2b[i] = g2b[i];
        pwh[i] = wh[i];
    }
    if (tid < TILE_M) {
        u_s[tid] = u[row0 + tid];
        rsum[tid] = 0.0f; rssq[tid] = 0.0f; oacc[tid] = 0.0f;
    }
    for (int i = tid; i < TILE_M * 40; i += NTHREADS) {
        int r = i / 40, k4 = i - r * 40;
        float4 x = (k4 < 32) ? __ldg((const float4*)paths + (size_t)(row0 + r) * 32 + k4)
                             : __ldg((const float4*)Z_pat + (size_t)(row0 + r) * 8 + (k4 - 32));
        uint2 o; o.x = h2u(x.x, x.y); o.y = h2u(x.z, x.w);
        *(uint2*)(xbuf + r * XSB + k4 * 8) = o;
    }
    __syncthreads();

    const int lane = tid & 31, warp = tid >> 5;
    const int wm = warp & 1, wn = warp >> 1;
    const int qr = lane >> 2, qc = lane & 3;
    const int rb = wm * 32 + qr;
    const int cb = wn * 40 + 2 * qc;

    uint32_t xs_b = (uint32_t)__cvta_generic_to_shared(xbuf);
    uint32_t xaddr0 = xs_b + (uint32_t)((wm * 32 + (lane & 15)) * XSB + (lane >> 4) * 16);

    // ---- pass T: tacc = xp @ wt_p^T + PV[u][160:320]  (stays in registers) ----
    float tacc[2][5][4] = {};
    gemm_pass_h(tacc, g_WPK + (1 * 4 + wn) * 1600, xaddr0, lane);
    #pragma unroll
    for (int mf = 0; mf < 2; mf++) {
        int r = rb + mf * 16;
        const float* pv0 = g_PV + (size_t)u_s[r] * 320 + 160 + cb;
        const float* pv1 = g_PV + (size_t)u_s[r + 8] * 320 + 160 + cb;
        #pragma unroll
        for (int nf = 0; nf < 5; nf++) {
            float2 v0 = *(const float2*)(pv0 + nf * 8);
            float2 v1 = *(const float2*)(pv1 + nf * 8);
            tacc[mf][nf][0] += v0.x; tacc[mf][nf][1] += v0.y;
            tacc[mf][nf][2] += v1.x; tacc[mf][nf][3] += v1.y;
        }
    }

    // ---- pass 1: h1 = xp @ w1_p^T + PV[u][0:160], GN1, ReLU -> xbuf (fp16) ----
    {
        float acc[2][5][4] = {};
        gemm_pass_h(acc, g_WPK + (0 * 4 + wn) * 1600, xaddr0, lane);
        #pragma unroll
        for (int mf = 0; mf < 2; mf++) {
            int r = rb + mf * 16;
            const float* pv0 = g_PV + (size_t)u_s[r] * 320 + cb;
            const float* pv1 = g_PV + (size_t)u_s[r + 8] * 320 + cb;
            #pragma unroll
            for (int nf = 0; nf < 5; nf++) {
                float2 v0 = *(const float2*)(pv0 + nf * 8);
                float2 v1 = *(const float2*)(pv1 + nf * 8);
                acc[mf][nf][0] += v0.x; acc[mf][nf][1] += v0.y;
                acc[mf][nf][2] += v1.x; acc[mf][nf][3] += v1.y;
            }
        }
        #pragma unroll
        for (int mf = 0; mf < 2; mf++)
            #pragma unroll
            for (int h = 0; h < 2; h++) {
                float s = 0.0f, ss = 0.0f;
                #pragma unroll
                for (int nf = 0; nf < 5; nf++) {
                    float a0 = acc[mf][nf][2 * h], a1 = acc[mf][nf][2 * h + 1];
                    s += a0 + a1; ss += a0 * a0 + a1 * a1;
                }
                s  += __shfl_xor_sync(0xffffffffu, s, 1);
                ss += __shfl_xor_sync(0xffffffffu, ss, 1);
                s  += __shfl_xor_sync(0xffffffffu, s, 2);
                ss += __shfl_xor_sync(0xffffffffu, ss, 2);
                if (qc == 0) {
                    int r = rb + mf * 16 + 8 * h;
                    atomicAdd(&rsum[r], s);
                    atomicAdd(&rssq[r], ss);
                }
            }
        __syncthreads();
        #pragma unroll
        for (int mf = 0; mf < 2; mf++)
            #pragma unroll
            for (int h = 0; h < 2; h++) {
                int r = rb + mf * 16 + 8 * h;
                float mean = rsum[r] * (1.0f / 160.0f);
                float var  = rssq[r] * (1.0f / 160.0f) - mean * mean;
                float rstd = rsqrtf(var + 1e-5f);
                #pragma unroll
                for (int nf = 0; nf < 5; nf++) {
                    int col = cb + nf * 8;
                    float v0 = fmaxf((acc[mf][nf][2 * h]     - mean) * rstd * p1w[col]     + p1b[col],     0.f);
                    float v1 = fmaxf((acc[mf][nf][2 * h + 1] - mean) * rstd * p1w[col + 1] + p1b[col + 1], 0.f);
                    *(unsigned*)(xbuf + r * XSB + col * 2) = h2u(v0, v1);
                }
            }
    }
    __syncthreads();
    if (tid < TILE_M) { rsum[tid] = 0.0f; rssq[tid] = 0.0f; }
    __syncthreads();

    // ---- pass 2: h2 = h1r @ w2^T, GN2, +tacc, ReLU, head ----
    {
        float acc[2][5][4] = {};
        gemm_pass_h(acc, g_WPK + (2 * 4 + wn) * 1600, xaddr0, lane);
        #pragma unroll
        for (int mf = 0; mf < 2; mf++)
            #pragma unroll
            for (int h = 0; h < 2; h++) {
                float s = 0.0f, ss = 0.0f;
                #pragma unroll
                for (int nf = 0; nf < 5; nf++) {
                    float a0 = acc[mf][nf][2 * h], a1 = acc[mf][nf][2 * h + 1];
                    s += a0 + a1; ss += a0 * a0 + a1 * a1;
                }
                s  += __shfl_xor_sync(0xffffffffu, s, 1);
                ss += __shfl_xor_sync(0xffffffffu, ss, 1);
                s  += __shfl_xor_sync(0xffffffffu, s, 2);
                ss += __shfl_xor_sync(0xffffffffu, ss, 2);
                if (qc == 0) {
                    int r = rb + mf * 16 + 8 * h;
                    atomicAdd(&rsum[r], s);
                    atomicAdd(&rssq[r], ss);
                }
            }
        __syncthreads();
        #pragma unroll
        for (int mf = 0; mf < 2; mf++)
            #pragma unroll
            for (int h = 0; h < 2; h++) {
                int r = rb + mf * 16 + 8 * h;
                float mean = rsum[r] * (1.0f / 160.0f);
                float var  = rssq[r] * (1.0f / 160.0f) - mean * mean;
                float rstd = rsqrtf(var + 1e-5f);
                float part = 0.0f;
                #pragma unroll
                for (int nf = 0; nf < 5; nf++) {
                    int col = cb + nf * 8;
                    float v0 = (acc[mf][nf][2 * h]     - mean) * rstd * p2w[col]     + p2b[col]     + tacc[mf][nf][2 * h];
                    float v1 = (acc[mf][nf][2 * h + 1] - mean) * rstd * p2w[col + 1] + p2b[col + 1] + tacc[mf][nf][2 * h + 1];
                    v0 = fmaxf(v0, 0.0f);
                    v1 = fmaxf(v1, 0.0f);
                    part += v0 * pwh[col] + v1 * pwh[col + 1];
                }
                part += __shfl_xor_sync(0xffffffffu, part, 1);
                part += __shfl_xor_sync(0xffffffffu, part, 2);
                if (qc == 0) atomicAdd(&oacc[r], part);
            }
    }
    __syncthreads();
    if (tid < TILE_M) out[row0 + tid] = oacc[tid] + bh[0];
}

extern "C" void kernel_launch(void* const* d_in, const int* in_sizes, int n_in,
                              void* d_out, int out_size)
{
    const float* actors = (const float*)d_in[0];
    const float* paths  = (const float*)d_in[1];
    const float* Z_act  = (const float*)d_in[2];
    const float* Z_pat  = (const float*)d_in[3];
    const int*   u      = (const int*)  d_in[4];
    const float* w1     = (const float*)d_in[5];
    const float* w2     = (const float*)d_in[6];
    const float* wt     = (const float*)d_in[7];
    const float* g1w    = (const float*)d_in[8];
    const float* g1b    = (const float*)d_in[9];
    const float* g2w    = (const float*)d_in[10];
    const float* g2b    = (const float*)d_in[11];
    const float* wh     = (const float*)d_in[12];
    const float* bh     = (const float*)d_in[13];
    float* out = (float*)d_out;

    const int smem1 = VTILE * XSB;
    const int smem2 = TILE_M * XSB + 4 * TILE_M * 4 + 5 * 160 * 4;

    cudaFuncSetAttribute(veh_pre_kernel,   cudaFuncAttributeMaxDynamicSharedMemorySize, smem1);
    cudaFuncSetAttribute(path_main_kernel, cudaFuncAttributeMaxDynamicSharedMemorySize, smem2);

    pack_kernel<<<(32000 + 255) / 256, 256>>>(w1, w2, wt);
    veh_pre_kernel<<<(N_VEH + VTILE - 1) / VTILE, VTHREADS, smem1>>>(actors, Z_act);
    path_main_kernel<<<N_PATHS / TILE_M, NTHREADS, smem2>>>(
        paths, Z_pat, u, g1w, g1b, g2w, g2b, wh, bh, out);
}

// round 13
// speedup vs baseline: 2.1378x; 1.0710x over previous
#include <cuda_runtime.h>
#include <cuda_fp16.h>
#include <cuda_pipeline.h>
#include <cstdint>

#define N_VEH    40000
#define N_PATHS  400000
#define TILE_M   64
#define NTHREADS 256
#define VTILE    128
#define VTHREADS 512
#define XSB      336     // xbuf row stride in BYTES (168 halfs); conflict-free ldmatrix

// Per-vehicle partials [N_VEH][320]: cols 0..159 = w1_a @ va, 160..319 = wt_a @ va
__device__ float g_PV[(size_t)N_VEH * 320];
// Packed fp16 weights in m16n8k16 B-fragment order:
// [slice:5][wn:4][chunk:10][nf:5][lane:32] of uint2 {b0,b1}
// slice 0: w1[:,0:160], 1: wt[:,0:160], 2: w2, 3: w1[:,160:320], 4: wt[:,160:320]
__device__ __align__(16) uint2 g_WPK[32000];

__device__ __forceinline__ unsigned h2u(float lo, float hi) {
    __half2 h = __floats2half2_rn(lo, hi);
    return *(unsigned*)&h;
}

__device__ __forceinline__ void mma16(float* d, const unsigned* a, const unsigned* b) {
    asm volatile(
        "mma.sync.aligned.m16n8k16.row.col.f32.f16.f16.f32 "
        "{%0,%1,%2,%3}, {%4,%5,%6,%7}, {%8,%9}, {%0,%1,%2,%3};\n"
        : "+f"(d[0]), "+f"(d[1]), "+f"(d[2]), "+f"(d[3])
        : "r"(a[0]), "r"(a[1]), "r"(a[2]), "r"(a[3]), "r"(b[0]), "r"(b[1]));
}
__device__ __forceinline__ void ldsm4(unsigned a[4], uint32_t addr) {
    asm volatile("ldmatrix.sync.aligned.m8n8.x4.shared.b16 {%0,%1,%2,%3}, [%4];"
                 : "=r"(a[0]), "=r"(a[1]), "=r"(a[2]), "=r"(a[3]) : "r"(addr));
}

// Pack kernel: fp16 B fragments. One thread per uint2.
__global__ void pack_kernel(const float* __restrict__ w1, const float* __restrict__ w2,
                            const float* __restrict__ wt)
{
    int idx = blockIdx.x * blockDim.x + threadIdx.x;
    if (idx >= 32000) return;
    int lane = idx & 31;
    int nf   = (idx >> 5) % 5;
    int chunk= (idx / 160) % 10;
    int wn   = (idx / 1600) & 3;
    int slice= idx / 6400;

    const float* src; int gs, ko;
    switch (slice) {
        case 0: src = w1; gs = 320; ko = 0;   break;
        case 1: src = wt; gs = 320; ko = 0;   break;
        case 2: src = w2; gs = 160; ko = 0;   break;
        case 3: src = w1; gs = 320; ko = 160; break;
        default:src = wt; gs = 320; ko = 160; break;
    }
    int n = wn * 40 + nf * 8 + (lane >> 2);
    int kb = chunk * 16 + (lane & 3) * 2;
    const float* r = src + (size_t)n * gs + ko;
    uint2 o;
    o.x = h2u(r[kb],     r[kb + 1]);
    o.y = h2u(r[kb + 8], r[kb + 9]);
    g_WPK[idx] = o;
}

// Single GEMM pass (used by veh_pre): acc += X @ Wslice^T. B double-buffered from global.
__device__ __forceinline__ void gemm_pass_h(
    float acc[2][5][4],
    const uint2* __restrict__ pk, uint32_t xaddr0, int lane)
{
    const uint2* bp = pk + lane;
    uint2 b[2][5];
    #pragma unroll
    for (int j = 0; j < 5; j++) b[0][j] = __ldg(bp + j * 32);

    #pragma unroll
    for (int chunk = 0; chunk < 10; chunk++) {
        const int cur = chunk & 1;
        if (chunk < 9) {
            #pragma unroll
            for (int j = 0; j < 5; j++)
                b[cur ^ 1][j] = __ldg(bp + ((chunk + 1) * 5 + j) * 32);
        }
        unsigned a[2][4];
        uint32_t ad = xaddr0 + (uint32_t)(chunk * 32);
        ldsm4(a[0], ad);
        ldsm4(a[1], ad + 16 * XSB);
        #pragma unroll
        for (int mf = 0; mf < 2; mf++)
            #pragma unroll
            for (int nf = 0; nf < 5; nf++)
                mma16(acc[mf][nf], a[mf], &b[cur][nf].x);
    }
}

// Kernel 1: per-vehicle partial sums into g_PV (slices 3,4). 512 thr, 128-row tile.
__global__ void __launch_bounds__(VTHREADS, 1)
veh_pre_kernel(const float* __restrict__ actors, const float* __restrict__ Z_act)
{
    extern __shared__ char smem[];
    char* xbuf = smem;                       // 128 * 336 bytes (fp16)
    const int tid = threadIdx.x;
    const int v0 = blockIdx.x * VTILE;

    for (int i = tid; i < VTILE * 40; i += VTHREADS) {
        int r = i / 40, k4 = i - r * 40;
        int v = v0 + r;
        float4 x = make_float4(0.f, 0.f, 0.f, 0.f);
        if (v < N_VEH)
            x = (k4 < 32) ? __ldg((const float4*)actors + (size_t)v * 32 + k4)
                          : __ldg((const float4*)Z_act + (size_t)v * 8 + (k4 - 32));
        uint2 o; o.x = h2u(x.x, x.y); o.y = h2u(x.z, x.w);
        *(uint2*)(xbuf + r * XSB + k4 * 8) = o;
    }
    __syncthreads();

    const int lane = tid & 31, warp = tid >> 5;
    const int wm = warp & 3, wn = warp >> 2;
    const int qr = lane >> 2, qc = lane & 3;
    const int rb = wm * 32 + qr;
    const int cb = wn * 40 + 2 * qc;

    uint32_t xs_b = (uint32_t)__cvta_generic_to_shared(xbuf);
    uint32_t xaddr0 = xs_b + (uint32_t)((wm * 32 + (lane & 15)) * XSB + (lane >> 4) * 16);

    #pragma unroll 1
    for (int pass = 0; pass < 2; pass++) {
        const int slice = 3 + pass;
        const int coloff = pass ? 160 : 0;
        float acc[2][5][4] = {};
        gemm_pass_h(acc, g_WPK + (slice * 4 + wn) * 1600, xaddr0, lane);
        #pragma unroll
        for (int mf = 0; mf < 2; mf++) {
            int r = rb + mf * 16;
            int vA = v0 + r, vB = v0 + r + 8;
            #pragma unroll
            for (int nf = 0; nf < 5; nf++) {
                int c = cb + nf * 8;
                if (vA < N_VEH)
                    *(float2*)(g_PV + (size_t)vA * 320 + coloff + c) =
                        make_float2(acc[mf][nf][0], acc[mf][nf][1]);
                if (vB < N_VEH)
                    *(float2*)(g_PV + (size_t)vB * 320 + coloff + c) =
                        make_float2(acc[mf][nf][2], acc[mf][nf][3]);
            }
        }
    }
}

// Kernel 2: fused per-path pipeline. 256 thr, 64-row tile, 2 CTAs/SM.
// Merged T+1 GEMM (shared A, two acc streams), pass-2 B staged in smem, PV L2-prefetched.
__global__ void __launch_bounds__(NTHREADS, 2)
path_main_kernel(
    const float* __restrict__ paths, const float* __restrict__ Z_pat,
    const int* __restrict__ u,
    const float* __restrict__ g1w, const float* __restrict__ g1b,
    const float* __restrict__ g2w, const float* __restrict__ g2b,
    const float* __restrict__ wh, const float* __restrict__ bh,
    float* __restrict__ out)
{
    extern __shared__ char smem[];
    char*  xbuf = smem;                              // 64*336 = 21504 B
    char*  b2s  = smem + TILE_M * XSB;               // 51200 B (slice-2 B image)
    int*   u_s  = (int*)(b2s + 51200);               // 64
    float* rsum = (float*)(u_s + TILE_M);            // 64
    float* rssq = rsum + TILE_M;
    float* rsum2= rssq + TILE_M;
    float* rssq2= rsum2 + TILE_M;
    float* oacc = rssq2 + TILE_M;
    float* p1w = oacc + TILE_M;                      // 5 x 160 params
    float* p1b = p1w + 160;
    float* p2w = p1b + 160;
    float* p2b = p2w + 160;
    float* pwh = p2b + 160;

    const int tid = threadIdx.x;
    const int row0 = blockIdx.x * TILE_M;

    // --- early: PV L2 prefetch (warms both epilogue gathers) ---
    {
        int r = tid >> 2, p = tid & 3;
        int uv = __ldg(u + row0 + r);
        const char* base = (const char*)(g_PV + (size_t)uv * 320) + p * 320;
        asm volatile("prefetch.global.L2 [%0];" :: "l"(base));
        asm volatile("prefetch.global.L2 [%0];" :: "l"(base + 128));
        asm volatile("prefetch.global.L2 [%0];" :: "l"(base + 256));
        if (p == 0) u_s[r] = uv;
    }

    for (int i = tid; i < 160; i += NTHREADS) {
        p1w[i] = g1w[i]; p1b[i] = g1b[i];
        p2w[i] = g2w[i]; p2b[i] = g2b[i];
        pwh[i] = wh[i];
    }
    if (tid < TILE_M) {
        rsum[tid] = 0.0f; rssq[tid] = 0.0f;
        rsum2[tid] = 0.0f; rssq2[tid] = 0.0f; oacc[tid] = 0.0f;
    }
    for (int i = tid; i < TILE_M * 40; i += NTHREADS) {
        int r = i / 40, k4 = i - r * 40;
        float4 x = (k4 < 32) ? __ldg((const float4*)paths + (size_t)(row0 + r) * 32 + k4)
                             : __ldg((const float4*)Z_pat + (size_t)(row0 + r) * 8 + (k4 - 32));
        uint2 o; o.x = h2u(x.x, x.y); o.y = h2u(x.z, x.w);
        *(uint2*)(xbuf + r * XSB + k4 * 8) = o;
    }
    // --- stage pass-2 B slice into smem asynchronously (hidden behind merged pass) ---
    {
        const char* src = (const char*)(g_WPK + 2 * 6400);
        for (int off = tid * 16; off < 51200; off += NTHREADS * 16)
            __pipeline_memcpy_async(b2s + off, src + off, 16);
        __pipeline_commit();
    }
    __syncthreads();

    const int lane = tid & 31, warp = tid >> 5;
    const int wm = warp & 1, wn = warp >> 1;
    const int qr = lane >> 2, qc = lane & 3;
    const int rb = wm * 32 + qr;
    const int cb = wn * 40 + 2 * qc;

    uint32_t xs_b = (uint32_t)__cvta_generic_to_shared(xbuf);
    uint32_t xaddr0 = xs_b + (uint32_t)((wm * 32 + (lane & 15)) * XSB + (lane >> 4) * 16);

    // ---- merged pass T + 1: tacc = xp @ wt_p^T ; acc1 = xp @ w1_p^T ----
    float tacc[2][5][4] = {};
    float acc1[2][5][4] = {};
    {
        const uint2* bpT = g_WPK + (1 * 4 + wn) * 1600 + lane;  // slice 1 (wt_p)
        const uint2* bp1 = g_WPK + (0 * 4 + wn) * 1600 + lane;  // slice 0 (w1_p)
        uint2 bT[5], b1[5];
        #pragma unroll
        for (int j = 0; j < 5; j++) bT[j] = __ldg(bpT + j * 32);

        #pragma unroll
        for (int chunk = 0; chunk < 10; chunk++) {
            #pragma unroll
            for (int j = 0; j < 5; j++) b1[j] = __ldg(bp1 + (chunk * 5 + j) * 32);
            unsigned a[2][4];
            uint32_t ad = xaddr0 + (uint32_t)(chunk * 32);
            ldsm4(a[0], ad);
            ldsm4(a[1], ad + 16 * XSB);
            #pragma unroll
            for (int mf = 0; mf < 2; mf++)
                #pragma unroll
                for (int nf = 0; nf < 5; nf++)
                    mma16(tacc[mf][nf], a[mf], &bT[nf].x);
            if (chunk < 9) {
                #pragma unroll
                for (int j = 0; j < 5; j++) bT[j] = __ldg(bpT + ((chunk + 1) * 5 + j) * 32);
            }
            #pragma unroll
            for (int mf = 0; mf < 2; mf++)
                #pragma unroll
                for (int nf = 0; nf < 5; nf++)
                    mma16(acc1[mf][nf], a[mf], &b1[nf].x);
        }
    }

    // PV adds for both streams
    #pragma unroll
    for (int mf = 0; mf < 2; mf++) {
        int r = rb + mf * 16;
        const float* pvA = g_PV + (size_t)u_s[r] * 320;
        const float* pvB = g_PV + (size_t)u_s[r + 8] * 320;
        #pragma unroll
        for (int nf = 0; nf < 5; nf++) {
            int c = cb + nf * 8;
            float2 t0 = *(const float2*)(pvA + 160 + c);
            float2 t1 = *(const float2*)(pvB + 160 + c);
            tacc[mf][nf][0] += t0.x; tacc[mf][nf][1] += t0.y;
            tacc[mf][nf][2] += t1.x; tacc[mf][nf][3] += t1.y;
            float2 h0 = *(const float2*)(pvA + c);
            float2 h1 = *(const float2*)(pvB + c);
            acc1[mf][nf][0] += h0.x; acc1[mf][nf][1] += h0.y;
            acc1[mf][nf][2] += h1.x; acc1[mf][nf][3] += h1.y;
        }
    }

    // ---- GN1 + ReLU -> xbuf (fp16) ----
    #pragma unroll
    for (int mf = 0; mf < 2; mf++)
        #pragma unroll
        for (int h = 0; h < 2; h++) {
            float s = 0.0f, ss = 0.0f;
            #pragma unroll
            for (int nf = 0; nf < 5; nf++) {
                float a0 = acc1[mf][nf][2 * h], a1 = acc1[mf][nf][2 * h + 1];
                s += a0 + a1; ss += a0 * a0 + a1 * a1;
            }
            s  += __shfl_xor_sync(0xffffffffu, s, 1);
            ss += __shfl_xor_sync(0xffffffffu, ss, 1);
            s  += __shfl_xor_sync(0xffffffffu, s, 2);
            ss += __shfl_xor_sync(0xffffffffu, ss, 2);
            if (qc == 0) {
                int r = rb + mf * 16 + 8 * h;
                atomicAdd(&rsum[r], s);
                atomicAdd(&rssq[r], ss);
            }
        }
    __syncthreads();
    #pragma unroll
    for (int mf = 0; mf < 2; mf++)
        #pragma unroll
        for (int h = 0; h < 2; h++) {
            int r = rb + mf * 16 + 8 * h;
            float mean = rsum[r] * (1.0f / 160.0f);
            float var  = rssq[r] * (1.0f / 160.0f) - mean * mean;
            float rstd = rsqrtf(var + 1e-5f);
            #pragma unroll
            for (int nf = 0; nf < 5; nf++) {
                int col = cb + nf * 8;
                float v0 = fmaxf((acc1[mf][nf][2 * h]     - mean) * rstd * p1w[col]     + p1b[col],     0.f);
                float v1 = fmaxf((acc1[mf][nf][2 * h + 1] - mean) * rstd * p1w[col + 1] + p1b[col + 1], 0.f);
                *(unsigned*)(xbuf + r * XSB + col * 2) = h2u(v0, v1);
            }
        }
    __pipeline_wait_prior(0);
    __syncthreads();

    // ---- pass 2: h2 = h1r @ w2^T (B from smem), GN2, +tacc, ReLU, head ----
    {
        float acc[2][5][4] = {};
        {
            const char* bp = b2s + wn * 12800 + lane * 8;
            #pragma unroll
            for (int chunk = 0; chunk < 10; chunk++) {
                uint2 b[5];
                #pragma unroll
                for (int j = 0; j < 5; j++)
                    b[j] = *(const uint2*)(bp + (chunk * 5 + j) * 256);
                unsigned a[2][4];
                uint32_t ad = xaddr0 + (uint32_t)(chunk * 32);
                ldsm4(a[0], ad);
                ldsm4(a[1], ad + 16 * XSB);
                #pragma unroll
                for (int mf = 0; mf < 2; mf++)
                    #pragma unroll
                    for (int nf = 0; nf < 5; nf++)
                        mma16(acc[mf][nf], a[mf], &b[nf].x);
            }
        }
        #pragma unroll
        for (int mf = 0; mf < 2; mf++)
            #pragma unroll
            for (int h = 0; h < 2; h++) {
                float s = 0.0f, ss = 0.0f;
                #pragma unroll
                for (int nf = 0; nf < 5; nf++) {
                    float a0 = acc[mf][nf][2 * h], a1 = acc[mf][nf][2 * h + 1];
                    s += a0 + a1; ss += a0 * a0 + a1 * a1;
                }
                s  += __shfl_xor_sync(0xffffffffu, s, 1);
                ss += __shfl_xor_sync(0xffffffffu, ss, 1);
                s  += __shfl_xor_sync(0xffffffffu, s, 2);
                ss += __shfl_xor_sync(0xffffffffu, ss, 2);
                if (qc == 0) {
                    int r = rb + mf * 16 + 8 * h;
                    atomicAdd(&rsum2[r], s);
                    atomicAdd(&rssq2[r], ss);
                }
            }
        __syncthreads();
        #pragma unroll
        for (int mf = 0; mf < 2; mf++)
            #pragma unroll
            for (int h = 0; h < 2; h++) {
                int r = rb + mf * 16 + 8 * h;
                float mean = rsum2[r] * (1.0f / 160.0f);
                float var  = rssq2[r] * (1.0f / 160.0f) - mean * mean;
                float rstd = rsqrtf(var + 1e-5f);
                float part = 0.0f;
                #pragma unroll
                for (int nf = 0; nf < 5; nf++) {
                    int col = cb + nf * 8;
                    float v0 = (acc[mf][nf][2 * h]     - mean) * rstd * p2w[col]     + p2b[col]     + tacc[mf][nf][2 * h];
                    float v1 = (acc[mf][nf][2 * h + 1] - mean) * rstd * p2w[col + 1] + p2b[col + 1] + tacc[mf][nf][2 * h + 1];
                    v0 = fmaxf(v0, 0.0f);
                    v1 = fmaxf(v1, 0.0f);
                    part += v0 * pwh[col] + v1 * pwh[col + 1];
                }
                part += __shfl_xor_sync(0xffffffffu, part, 1);
                part += __shfl_xor_sync(0xffffffffu, part, 2);
                if (qc == 0) atomicAdd(&oacc[r], part);
            }
    }
    __syncthreads();
    if (tid < TILE_M) out[row0 + tid] = oacc[tid] + bh[0];
}

extern "C" void kernel_launch(void* const* d_in, const int* in_sizes, int n_in,
                              void* d_out, int out_size)
{
    const float* actors = (const float*)d_in[0];
    const float* paths  = (const float*)d_in[1];
    const float* Z_act  = (const float*)d_in[2];
    const float* Z_pat  = (const float*)d_in[3];
    const int*   u      = (const int*)  d_in[4];
    const float* w1     = (const float*)d_in[5];
    const float* w2     = (const float*)d_in[6];
    const float* wt     = (const float*)d_in[7];
    const float* g1w    = (const float*)d_in[8];
    const float* g1b    = (const float*)d_in[9];
    const float* g2w    = (const float*)d_in[10];
    const float* g2b    = (const float*)d_in[11];
    const float* wh     = (const float*)d_in[12];
    const float* bh     = (const float*)d_in[13];
    float* out = (float*)d_out;

    const int smem1 = VTILE * XSB;
    const int smem2 = TILE_M * XSB + 51200 + TILE_M * 4 + 5 * TILE_M * 4 + 5 * 160 * 4;

    cudaFuncSetAttribute(veh_pre_kernel,   cudaFuncAttributeMaxDynamicSharedMemorySize, smem1);
    cudaFuncSetAttribute(path_main_kernel, cudaFuncAttributeMaxDynamicSharedMemorySize, smem2);

    pack_kernel<<<(32000 + 255) / 256, 256>>>(w1, w2, wt);
    veh_pre_kernel<<<(N_VEH + VTILE - 1) / VTILE, VTHREADS, smem1>>>(actors, Z_act);
    path_main_kernel<<<N_PATHS / TILE_M, NTHREADS, smem2>>>(
        paths, Z_pat, u, g1w, g1b, g2w, g2b, wh, bh, out);
}

// round 14
// speedup vs baseline: 2.8023x; 1.3109x over previous
#include <cuda_runtime.h>
#include <cuda_fp16.h>
#include <cuda_pipeline.h>
#include <cstdint>

#define N_VEH    40000
#define N_PATHS  400000
#define N_TILES  6250
#define TILE_M   64
#define NTHREADS 256
#define VTILE    128
#define VTHREADS 512
#define XSB      336     // xbuf row stride in BYTES (168 halfs); conflict-free ldmatrix

// Per-vehicle partials [N_VEH][320]: cols 0..159 = w1_a @ va, 160..319 = wt_a @ va
__device__ float g_PV[(size_t)N_VEH * 320];
// Packed fp16 weights in m16n8k16 B-fragment order:
// [slice:5][wn:4][chunk:10][nf:5][lane:32] of uint2 {b0,b1}
// slice 0: w1[:,0:160], 1: wt[:,0:160], 2: w2, 3: w1[:,160:320], 4: wt[:,160:320]
__device__ __align__(16) uint2 g_WPK[32000];

__device__ __forceinline__ unsigned h2u(float lo, float hi) {
    __half2 h = __floats2half2_rn(lo, hi);
    return *(unsigned*)&h;
}

__device__ __forceinline__ void mma16(float* d, const unsigned* a, const unsigned* b) {
    asm volatile(
        "mma.sync.aligned.m16n8k16.row.col.f32.f16.f16.f32 "
        "{%0,%1,%2,%3}, {%4,%5,%6,%7}, {%8,%9}, {%0,%1,%2,%3};\n"
        : "+f"(d[0]), "+f"(d[1]), "+f"(d[2]), "+f"(d[3])
        : "r"(a[0]), "r"(a[1]), "r"(a[2]), "r"(a[3]), "r"(b[0]), "r"(b[1]));
}
__device__ __forceinline__ void ldsm4(unsigned a[4], uint32_t addr) {
    asm volatile("ldmatrix.sync.aligned.m8n8.x4.shared.b16 {%0,%1,%2,%3}, [%4];"
                 : "=r"(a[0]), "=r"(a[1]), "=r"(a[2]), "=r"(a[3]) : "r"(addr));
}
__device__ __forceinline__ void pref_l2(const void* p) {
    asm volatile("prefetch.global.L2 [%0];" :: "l"(p));
}

// Pack kernel: fp16 B fragments. One thread per uint2.
__global__ void pack_kernel(const float* __restrict__ w1, const float* __restrict__ w2,
                            const float* __restrict__ wt)
{
    int idx = blockIdx.x * blockDim.x + threadIdx.x;
    if (idx >= 32000) return;
    int lane = idx & 31;
    int nf   = (idx >> 5) % 5;
    int chunk= (idx / 160) % 10;
    int wn   = (idx / 1600) & 3;
    int slice= idx / 6400;

    const float* src; int gs, ko;
    switch (slice) {
        case 0: src = w1; gs = 320; ko = 0;   break;
        case 1: src = wt; gs = 320; ko = 0;   break;
        case 2: src = w2; gs = 160; ko = 0;   break;
        case 3: src = w1; gs = 320; ko = 160; break;
        default:src = wt; gs = 320; ko = 160; break;
    }
    int n = wn * 40 + nf * 8 + (lane >> 2);
    int kb = chunk * 16 + (lane & 3) * 2;
    const float* r = src + (size_t)n * gs + ko;
    uint2 o;
    o.x = h2u(r[kb],     r[kb + 1]);
    o.y = h2u(r[kb + 8], r[kb + 9]);
    g_WPK[idx] = o;
}

// Single GEMM pass (used by veh_pre): acc += X @ Wslice^T. B double-buffered from global.
__device__ __forceinline__ void gemm_pass_h(
    float acc[2][5][4],
    const uint2* __restrict__ pk, uint32_t xaddr0, int lane)
{
    const uint2* bp = pk + lane;
    uint2 b[2][5];
    #pragma unroll
    for (int j = 0; j < 5; j++) b[0][j] = __ldg(bp + j * 32);

    #pragma unroll
    for (int chunk = 0; chunk < 10; chunk++) {
        const int cur = chunk & 1;
        if (chunk < 9) {
            #pragma unroll
            for (int j = 0; j < 5; j++)
                b[cur ^ 1][j] = __ldg(bp + ((chunk + 1) * 5 + j) * 32);
        }
        unsigned a[2][4];
        uint32_t ad = xaddr0 + (uint32_t)(chunk * 32);
        ldsm4(a[0], ad);
        ldsm4(a[1], ad + 16 * XSB);
        #pragma unroll
        for (int mf = 0; mf < 2; mf++)
            #pragma unroll
            for (int nf = 0; nf < 5; nf++)
                mma16(acc[mf][nf], a[mf], &b[cur][nf].x);
    }
}

// Kernel 1: per-vehicle partial sums into g_PV (slices 3,4). 512 thr, 128-row tile.
__global__ void __launch_bounds__(VTHREADS, 1)
veh_pre_kernel(const float* __restrict__ actors, const float* __restrict__ Z_act)
{
    extern __shared__ char smem[];
    char* xbuf = smem;                       // 128 * 336 bytes (fp16)
    const int tid = threadIdx.x;
    const int v0 = blockIdx.x * VTILE;

    for (int i = tid; i < VTILE * 40; i += VTHREADS) {
        int r = i / 40, k4 = i - r * 40;
        int v = v0 + r;
        float4 x = make_float4(0.f, 0.f, 0.f, 0.f);
        if (v < N_VEH)
            x = (k4 < 32) ? __ldg((const float4*)actors + (size_t)v * 32 + k4)
                          : __ldg((const float4*)Z_act + (size_t)v * 8 + (k4 - 32));
        uint2 o; o.x = h2u(x.x, x.y); o.y = h2u(x.z, x.w);
        *(uint2*)(xbuf + r * XSB + k4 * 8) = o;
    }
    __syncthreads();

    const int lane = tid & 31, warp = tid >> 5;
    const int wm = warp & 3, wn = warp >> 2;
    const int qr = lane >> 2, qc = lane & 3;
    const int rb = wm * 32 + qr;
    const int cb = wn * 40 + 2 * qc;

    uint32_t xs_b = (uint32_t)__cvta_generic_to_shared(xbuf);
    uint32_t xaddr0 = xs_b + (uint32_t)((wm * 32 + (lane & 15)) * XSB + (lane >> 4) * 16);

    #pragma unroll 1
    for (int pass = 0; pass < 2; pass++) {
        const int slice = 3 + pass;
        const int coloff = pass ? 160 : 0;
        float acc[2][5][4] = {};
        gemm_pass_h(acc, g_WPK + (slice * 4 + wn) * 1600, xaddr0, lane);
        #pragma unroll
        for (int mf = 0; mf < 2; mf++) {
            int r = rb + mf * 16;
            int vA = v0 + r, vB = v0 + r + 8;
            #pragma unroll
            for (int nf = 0; nf < 5; nf++) {
                int c = cb + nf * 8;
                if (vA < N_VEH)
                    *(float2*)(g_PV + (size_t)vA * 320 + coloff + c) =
                        make_float2(acc[mf][nf][0], acc[mf][nf][1]);
                if (vB < N_VEH)
                    *(float2*)(g_PV + (size_t)vB * 320 + coloff + c) =
                        make_float2(acc[mf][nf][2], acc[mf][nf][3]);
            }
        }
    }
}

// Kernel 2: PERSISTENT fused per-path pipeline. 256 thr, 2 CTAs/SM, grid-stride tile loop.
// b2s staged once per CTA; next tile's inputs L2-prefetched during current tile.
__global__ void __launch_bounds__(NTHREADS, 2)
path_main_kernel(
    const float* __restrict__ paths, const float* __restrict__ Z_pat,
    const int* __restrict__ u,
    const float* __restrict__ g1w, const float* __restrict__ g1b,
    const float* __restrict__ g2w, const float* __restrict__ g2b,
    const float* __restrict__ wh, const float* __restrict__ bh,
    float* __restrict__ out)
{
    extern __shared__ char smem[];
    char*  xbuf = smem;                              // 64*336 = 21504 B
    char*  b2s  = smem + TILE_M * XSB;               // 51200 B (slice-2 B image)
    int*   u_s  = (int*)(b2s + 51200);               // 64
    float* rsum = (float*)(u_s + TILE_M);            // 64
    float* rssq = rsum + TILE_M;
    float* rsum2= rssq + TILE_M;
    float* rssq2= rsum2 + TILE_M;
    float* oacc = rssq2 + TILE_M;
    float* p1w = oacc + TILE_M;                      // 5 x 160 params
    float* p1b = p1w + 160;
    float* p2w = p1b + 160;
    float* p2b = p2w + 160;
    float* pwh = p2b + 160;

    const int tid = threadIdx.x;
    const int lane = tid & 31, warp = tid >> 5;
    const int wm = warp & 1, wn = warp >> 1;
    const int qr = lane >> 2, qc = lane & 3;
    const int rb = wm * 32 + qr;
    const int cb = wn * 40 + 2 * qc;

    uint32_t xs_b = (uint32_t)__cvta_generic_to_shared(xbuf);
    uint32_t xaddr0 = xs_b + (uint32_t)((wm * 32 + (lane & 15)) * XSB + (lane >> 4) * 16);

    // ---- prologue (once per CTA) ----
    {
        const char* src = (const char*)(g_WPK + 2 * 6400);
        for (int off = tid * 16; off < 51200; off += NTHREADS * 16)
            __pipeline_memcpy_async(b2s + off, src + off, 16);
        __pipeline_commit();
    }
    for (int i = tid; i < 160; i += NTHREADS) {
        p1w[i] = g1w[i]; p1b[i] = g1b[i];
        p2w[i] = g2w[i]; p2b[i] = g2b[i];
        pwh[i] = wh[i];
    }
    if (tid < TILE_M) {
        rsum[tid] = 0.0f; rssq[tid] = 0.0f;
        rsum2[tid] = 0.0f; rssq2[tid] = 0.0f; oacc[tid] = 0.0f;
    }
    __pipeline_wait_prior(0);

    const float bhv = __ldg(bh);

    #pragma unroll 1
    for (int tile = blockIdx.x; tile < N_TILES; tile += gridDim.x) {
        const int row0 = tile * TILE_M;

        // ---- stage tile inputs + PV L2 prefetch ----
        {
            int r = tid >> 2, p = tid & 3;
            int uv = __ldg(u + row0 + r);
            const char* base = (const char*)(g_PV + (size_t)uv * 320) + p * 320;
            pref_l2(base); pref_l2(base + 128); pref_l2(base + 256);
            if (p == 0) u_s[r] = uv;
        }
        for (int i = tid; i < TILE_M * 40; i += NTHREADS) {
            int r = i / 40, k4 = i - r * 40;
            float4 x = (k4 < 32) ? __ldg((const float4*)paths + (size_t)(row0 + r) * 32 + k4)
                                 : __ldg((const float4*)Z_pat + (size_t)(row0 + r) * 8 + (k4 - 32));
            uint2 o; o.x = h2u(x.x, x.y); o.y = h2u(x.z, x.w);
            *(uint2*)(xbuf + r * XSB + k4 * 8) = o;
        }
        __syncthreads();

        // ---- merged pass T + 1: tacc = xp @ wt_p^T ; acc1 = xp @ w1_p^T ----
        float tacc[2][5][4] = {};
        float acc1[2][5][4] = {};
        {
            const uint2* bpT = g_WPK + (1 * 4 + wn) * 1600 + lane;  // slice 1 (wt_p)
            const uint2* bp1 = g_WPK + (0 * 4 + wn) * 1600 + lane;  // slice 0 (w1_p)
            uint2 bT[5], b1[5];
            #pragma unroll
            for (int j = 0; j < 5; j++) bT[j] = __ldg(bpT + j * 32);

            #pragma unroll
            for (int chunk = 0; chunk < 10; chunk++) {
                #pragma unroll
                for (int j = 0; j < 5; j++) b1[j] = __ldg(bp1 + (chunk * 5 + j) * 32);
                unsigned a[2][4];
                uint32_t ad = xaddr0 + (uint32_t)(chunk * 32);
                ldsm4(a[0], ad);
                ldsm4(a[1], ad + 16 * XSB);
                #pragma unroll
                for (int mf = 0; mf < 2; mf++)
                    #pragma unroll
                    for (int nf = 0; nf < 5; nf++)
                        mma16(tacc[mf][nf], a[mf], &bT[nf].x);
                if (chunk < 9) {
                    #pragma unroll
                    for (int j = 0; j < 5; j++) bT[j] = __ldg(bpT + ((chunk + 1) * 5 + j) * 32);
                }
                #pragma unroll
                for (int mf = 0; mf < 2; mf++)
                    #pragma unroll
                    for (int nf = 0; nf < 5; nf++)
                        mma16(acc1[mf][nf], a[mf], &b1[nf].x);
            }
        }

        // PV adds for both streams
        #pragma unroll
        for (int mf = 0; mf < 2; mf++) {
            int r = rb + mf * 16;
            const float* pvA = g_PV + (size_t)u_s[r] * 320;
            const float* pvB = g_PV + (size_t)u_s[r + 8] * 320;
            #pragma unroll
            for (int nf = 0; nf < 5; nf++) {
                int c = cb + nf * 8;
                float2 t0 = *(const float2*)(pvA + 160 + c);
                float2 t1 = *(const float2*)(pvB + 160 + c);
                tacc[mf][nf][0] += t0.x; tacc[mf][nf][1] += t0.y;
                tacc[mf][nf][2] += t1.x; tacc[mf][nf][3] += t1.y;
                float2 h0 = *(const float2*)(pvA + c);
                float2 h1 = *(const float2*)(pvB + c);
                acc1[mf][nf][0] += h0.x; acc1[mf][nf][1] += h0.y;
                acc1[mf][nf][2] += h1.x; acc1[mf][nf][3] += h1.y;
            }
        }

        // ---- prefetch next tile's inputs into L2 ----
        {
            int nt = tile + gridDim.x;
            if (nt < N_TILES) {
                int nrow0 = nt * TILE_M;
                int r = tid >> 2, p = tid & 3;
                pref_l2((const char*)(paths + (size_t)(nrow0 + r) * 128) + p * 128);
                if (p == 0) pref_l2(Z_pat + (size_t)(nrow0 + r) * 32);
                if (tid < 2) pref_l2((const char*)(u + nrow0) + tid * 128);
            }
        }

        // ---- GN1 + ReLU -> xbuf (fp16) ----
        #pragma unroll
        for (int mf = 0; mf < 2; mf++)
            #pragma unroll
            for (int h = 0; h < 2; h++) {
                float s = 0.0f, ss = 0.0f;
                #pragma unroll
                for (int nf = 0; nf < 5; nf++) {
                    float a0 = acc1[mf][nf][2 * h], a1 = acc1[mf][nf][2 * h + 1];
                    s += a0 + a1; ss += a0 * a0 + a1 * a1;
                }
                s  += __shfl_xor_sync(0xffffffffu, s, 1);
                ss += __shfl_xor_sync(0xffffffffu, ss, 1);
                s  += __shfl_xor_sync(0xffffffffu, s, 2);
                ss += __shfl_xor_sync(0xffffffffu, ss, 2);
                if (qc == 0) {
                    int r = rb + mf * 16 + 8 * h;
                    atomicAdd(&rsum[r], s);
                    atomicAdd(&rssq[r], ss);
                }
            }
        __syncthreads();
        #pragma unroll
        for (int mf = 0; mf < 2; mf++)
            #pragma unroll
            for (int h = 0; h < 2; h++) {
                int r = rb + mf * 16 + 8 * h;
                float mean = rsum[r] * (1.0f / 160.0f);
                float var  = rssq[r] * (1.0f / 160.0f) - mean * mean;
                float rstd = rsqrtf(var + 1e-5f);
                #pragma unroll
                for (int nf = 0; nf < 5; nf++) {
                    int col = cb + nf * 8;
                    float v0 = fmaxf((acc1[mf][nf][2 * h]     - mean) * rstd * p1w[col]     + p1b[col],     0.f);
                    float v1 = fmaxf((acc1[mf][nf][2 * h + 1] - mean) * rstd * p1w[col + 1] + p1b[col + 1], 0.f);
                    *(unsigned*)(xbuf + r * XSB + col * 2) = h2u(v0, v1);
                }
            }
        __syncthreads();

        // ---- pass 2: h2 = h1r @ w2^T (B from smem), GN2, +tacc, ReLU, head ----
        {
            float acc[2][5][4] = {};
            {
                const char* bp = b2s + wn * 12800 + lane * 8;
                #pragma unroll
                for (int chunk = 0; chunk < 10; chunk++) {
                    uint2 b[5];
                    #pragma unroll
                    for (int j = 0; j < 5; j++)
                        b[j] = *(const uint2*)(bp + (chunk * 5 + j) * 256);
                    unsigned a[2][4];
                    uint32_t ad = xaddr0 + (uint32_t)(chunk * 32);
                    ldsm4(a[0], ad);
                    ldsm4(a[1], ad + 16 * XSB);
                    #pragma unroll
                    for (int mf = 0; mf < 2; mf++)
                        #pragma unroll
                        for (int nf = 0; nf < 5; nf++)
                            mma16(acc[mf][nf], a[mf], &b[nf].x);
                }
            }
            #pragma unroll
            for (int mf = 0; mf < 2; mf++)
                #pragma unroll
                for (int h = 0; h < 2; h++) {
                    float s = 0.0f, ss = 0.0f;
                    #pragma unroll
                    for (int nf = 0; nf < 5; nf++) {
                        float a0 = acc[mf][nf][2 * h], a1 = acc[mf][nf][2 * h + 1];
                        s += a0 + a1; ss += a0 * a0 + a1 * a1;
                    }
                    s  += __shfl_xor_sync(0xffffffffu, s, 1);
                    ss += __shfl_xor_sync(0xffffffffu, ss, 1);
                    s  += __shfl_xor_sync(0xffffffffu, s, 2);
                    ss += __shfl_xor_sync(0xffffffffu, ss, 2);
                    if (qc == 0) {
                        int r = rb + mf * 16 + 8 * h;
                        atomicAdd(&rsum2[r], s);
                        atomicAdd(&rssq2[r], ss);
                    }
                }
            __syncthreads();
            #pragma unroll
            for (int mf = 0; mf < 2; mf++)
                #pragma unroll
                for (int h = 0; h < 2; h++) {
                    int r = rb + mf * 16 + 8 * h;
                    float mean = rsum2[r] * (1.0f / 160.0f);
                    float var  = rssq2[r] * (1.0f / 160.0f) - mean * mean;
                    float rstd = rsqrtf(var + 1e-5f);
                    float part = 0.0f;
                    #pragma unroll
                    for (int nf = 0; nf < 5; nf++) {
                        int col = cb + nf * 8;
                        float v0 = (acc[mf][nf][2 * h]     - mean) * rstd * p2w[col]     + p2b[col]     + tacc[mf][nf][2 * h];
                        float v1 = (acc[mf][nf][2 * h + 1] - mean) * rstd * p2w[col + 1] + p2b[col + 1] + tacc[mf][nf][2 * h + 1];
                        v0 = fmaxf(v0, 0.0f);
                        v1 = fmaxf(v1, 0.0f);
                        part += v0 * pwh[col] + v1 * pwh[col + 1];
                    }
                    part += __shfl_xor_sync(0xffffffffu, part, 1);
                    part += __shfl_xor_sync(0xffffffffu, part, 2);
                    if (qc == 0) atomicAdd(&oacc[r], part);
                }
        }
        __syncthreads();
        // out store + stat re-zero for next tile (consumers all behind the barrier above)
        if (tid < TILE_M) {
            out[row0 + tid] = oacc[tid] + bhv;
            rsum[tid] = 0.0f; rssq[tid] = 0.0f;
            rsum2[tid] = 0.0f; rssq2[tid] = 0.0f; oacc[tid] = 0.0f;
        }
        __syncthreads();
    }
}

extern "C" void kernel_launch(void* const* d_in, const int* in_sizes, int n_in,
                              void* d_out, int out_size)
{
    const float* actors = (const float*)d_in[0];
    const float* paths  = (const float*)d_in[1];
    const float* Z_act  = (const float*)d_in[2];
    const float* Z_pat  = (const float*)d_in[3];
    const int*   u      = (const int*)  d_in[4];
    const float* w1     = (const float*)d_in[5];
    const float* w2     = (const float*)d_in[6];
    const float* wt     = (const float*)d_in[7];
    const float* g1w    = (const float*)d_in[8];
    const float* g1b    = (const float*)d_in[9];
    const float* g2w    = (const float*)d_in[10];
    const float* g2b    = (const float*)d_in[11];
    const float* wh     = (const float*)d_in[12];
    const float* bh     = (const float*)d_in[13];
    float* out = (float*)d_out;

    const int smem1 = VTILE * XSB;
    const int smem2 = TILE_M * XSB + 51200 + TILE_M * 4 + 5 * TILE_M * 4 + 5 * 160 * 4;

    static int nsm = 0;
    if (nsm == 0) {
        cudaDeviceProp prop;
        cudaGetDeviceProperties(&prop, 0);
        nsm = prop.multiProcessorCount;
        cudaFuncSetAttribute(veh_pre_kernel,   cudaFuncAttributeMaxDynamicSharedMemorySize, smem1);
        cudaFuncSetAttribute(path_main_kernel, cudaFuncAttributeMaxDynamicSharedMemorySize, smem2);
    }

    pack_kernel<<<(32000 + 255) / 256, 256>>>(w1, w2, wt);
    veh_pre_kernel<<<(N_VEH + VTILE - 1) / VTILE, VTHREADS, smem1>>>(actors, Z_act);
    path_main_kernel<<<2 * nsm, NTHREADS, smem2>>>(
        paths, Z_pat, u, g1w, g1b, g2w, g2b, wh, bh, out);
}